// round 11
// baseline (speedup 1.0000x reference)
#include <cuda_runtime.h>
#include <math.h>

#define B_SZ      16
#define DIM       512
#define KEY_DIM   32
#define NUM_HEADS 8
#define RES       1024
#define NH_KD     256
#define D_HEAD    128
#define DH        1024
#define H_QKV     1536
#define EPS       1e-5f
#define SCALE_QK  0.17677669529663687f

// ---------------- static scratch ----------------
__device__ float g_qkv [B_SZ * H_QKV * RES];
__device__ float g_q   [B_SZ * NH_KD * RES];
__device__ float g_attn[134217728];           // 16*8*1024*1024 (unnormalized exp)
__device__ float g_av  [B_SZ * DH * RES];
__device__ float g_rsum[B_SZ * NUM_HEADS * RES];

// ---------------- tf32 helpers ----------------
__device__ __forceinline__ unsigned f2tf(float f) {
    unsigned r;
    asm("cvt.rna.tf32.f32 %0, %1;" : "=r"(r) : "f"(f));
    return r;
}
__device__ __forceinline__ float4 tf4(float4 v) {
    v.x = __uint_as_float(f2tf(v.x));
    v.y = __uint_as_float(f2tf(v.y));
    v.z = __uint_as_float(f2tf(v.z));
    v.w = __uint_as_float(f2tf(v.w));
    return v;
}
__device__ __forceinline__ void mma8(float c[4], const unsigned a[4],
                                     unsigned b0, unsigned b1) {
    asm("mma.sync.aligned.m16n8k8.row.col.f32.tf32.tf32.f32 "
        "{%0,%1,%2,%3},{%4,%5,%6,%7},{%8,%9},{%0,%1,%2,%3};"
        : "+f"(c[0]), "+f"(c[1]), "+f"(c[2]), "+f"(c[3])
        : "r"(a[0]), "r"(a[1]), "r"(a[2]), "r"(a[3]), "r"(b0), "r"(b1));
}

// ---------------- warp-tile mma step ----------------
// as: [m][k] stride AS; bs: [k][n] stride 136. One k8 step.
template<int AS>
__device__ __forceinline__ void mma_step(const float* __restrict__ as,
                                         const float* __restrict__ bs,
                                         int s, int wm, int wn, int lane,
                                         float acc[2][8][4])
{
    unsigned afr[2][4];
    const int kk = s * 8 + (lane & 3);
#pragma unroll
    for (int a_ = 0; a_ < 2; a_++) {
        int mr = wm * 32 + a_ * 16 + (lane >> 2);
        afr[a_][0] = __float_as_uint(as[mr * AS + kk]);
        afr[a_][1] = __float_as_uint(as[(mr + 8) * AS + kk]);
        afr[a_][2] = __float_as_uint(as[mr * AS + kk + 4]);
        afr[a_][3] = __float_as_uint(as[(mr + 8) * AS + kk + 4]);
    }
#pragma unroll
    for (int j = 0; j < 8; j++) {
        int col = wn * 64 + j * 8 + (lane >> 2);
        unsigned b0 = __float_as_uint(bs[(s * 8 + (lane & 3)) * 136 + col]);
        unsigned b1 = __float_as_uint(bs[(s * 8 + (lane & 3) + 4) * 136 + col]);
        mma8(acc[0][j], afr[0], b0, b1);
        mma8(acc[1][j], afr[1], b0, b1);
    }
}

// =====================================================================
// Channel GEMM+BN: 128x128 tile, double-buffered tf32 mma.
// =====================================================================
template<bool RELU_B>
__device__ __forceinline__ void gemm_body(
    const float* __restrict__ A, const float* __restrict__ Bm, float* __restrict__ C,
    int N, int K, size_t sB, size_t sC,
    const float* __restrict__ gg, const float* __restrict__ bbp,
    const float* __restrict__ mmp, const float* __restrict__ vvp)
{
    __shared__ float As[2][128 * 20];
    __shared__ float Bs[2][16 * 136];
    const float* Bb = Bm + (size_t)blockIdx.z * sB;
    float*       Cb = C  + (size_t)blockIdx.z * sC;

    const int t = threadIdx.x;
    const int lane = t & 31, warp = t >> 5;
    const int wm = warp >> 1, wn = warp & 1;
    const int row0 = blockIdx.y * 128, col0 = blockIdx.x * 128;

    const int am  = t >> 1;
    const int akc = (t & 1) * 8;
    const int bkr = t >> 5;
    const int bc4 = (t & 31) * 4;

    const float* Aptr  = A  + (size_t)(row0 + am) * K + akc;
    const float* Bptr0 = Bb + (size_t)bkr * N + col0 + bc4;
    const float* Bptr1 = Bb + (size_t)(bkr + 8) * N + col0 + bc4;

    float acc[2][8][4];
#pragma unroll
    for (int a_ = 0; a_ < 2; a_++)
#pragma unroll
        for (int j = 0; j < 8; j++)
#pragma unroll
            for (int u = 0; u < 4; u++) acc[a_][j][u] = 0.0f;

    {
        float4 a0 = *(const float4*)(Aptr);
        float4 a1 = *(const float4*)(Aptr + 4);
        *(float4*)(As[0] + am * 20 + akc)     = tf4(a0);
        *(float4*)(As[0] + am * 20 + akc + 4) = tf4(a1);
        float4 b0 = *(const float4*)(Bptr0);
        float4 b1 = *(const float4*)(Bptr1);
        if (RELU_B) {
            b0.x = fmaxf(b0.x, 0.f); b0.y = fmaxf(b0.y, 0.f); b0.z = fmaxf(b0.z, 0.f); b0.w = fmaxf(b0.w, 0.f);
            b1.x = fmaxf(b1.x, 0.f); b1.y = fmaxf(b1.y, 0.f); b1.z = fmaxf(b1.z, 0.f); b1.w = fmaxf(b1.w, 0.f);
        }
        *(float4*)(Bs[0] + bkr * 136 + bc4)       = tf4(b0);
        *(float4*)(Bs[0] + (bkr + 8) * 136 + bc4) = tf4(b1);
    }
    __syncthreads();

    int buf = 0;
    for (int k0 = 16; k0 < K; k0 += 16) {
        float4 pa0 = *(const float4*)(Aptr + k0);
        float4 pa1 = *(const float4*)(Aptr + k0 + 4);
        float4 pb0 = *(const float4*)(Bptr0 + (size_t)k0 * N);
        float4 pb1 = *(const float4*)(Bptr1 + (size_t)k0 * N);

        mma_step<20>(As[buf], Bs[buf], 0, wm, wn, lane, acc);
        mma_step<20>(As[buf], Bs[buf], 1, wm, wn, lane, acc);

        if (RELU_B) {
            pb0.x = fmaxf(pb0.x, 0.f); pb0.y = fmaxf(pb0.y, 0.f); pb0.z = fmaxf(pb0.z, 0.f); pb0.w = fmaxf(pb0.w, 0.f);
            pb1.x = fmaxf(pb1.x, 0.f); pb1.y = fmaxf(pb1.y, 0.f); pb1.z = fmaxf(pb1.z, 0.f); pb1.w = fmaxf(pb1.w, 0.f);
        }
        int nb = buf ^ 1;
        *(float4*)(As[nb] + am * 20 + akc)        = tf4(pa0);
        *(float4*)(As[nb] + am * 20 + akc + 4)    = tf4(pa1);
        *(float4*)(Bs[nb] + bkr * 136 + bc4)      = tf4(pb0);
        *(float4*)(Bs[nb] + (bkr + 8) * 136 + bc4)= tf4(pb1);
        __syncthreads();
        buf = nb;
    }
    mma_step<20>(As[buf], Bs[buf], 0, wm, wn, lane, acc);
    mma_step<20>(As[buf], Bs[buf], 1, wm, wn, lane, acc);

#pragma unroll
    for (int a_ = 0; a_ < 2; a_++) {
        int r0 = row0 + wm * 32 + a_ * 16 + (lane >> 2);
        int r1 = r0 + 8;
        float inv0  = gg[r0] * rsqrtf(vvp[r0] + EPS);
        float beta0 = bbp[r0] - mmp[r0] * inv0;
        float inv1  = gg[r1] * rsqrtf(vvp[r1] + EPS);
        float beta1 = bbp[r1] - mmp[r1] * inv1;
#pragma unroll
        for (int j = 0; j < 8; j++) {
            int col = col0 + wn * 64 + j * 8 + 2 * (lane & 3);
            float2 w0 = make_float2(acc[a_][j][0] * inv0 + beta0,
                                    acc[a_][j][1] * inv0 + beta0);
            float2 w1 = make_float2(acc[a_][j][2] * inv1 + beta1,
                                    acc[a_][j][3] * inv1 + beta1);
            *(float2*)&Cb[(size_t)r0 * N + col] = w0;
            *(float2*)&Cb[(size_t)r1 * N + col] = w1;
        }
    }
}

__global__ void __launch_bounds__(256, 2)
qkv_gemm_kernel(const float* __restrict__ x, const float* __restrict__ w,
                const float* __restrict__ g, const float* __restrict__ b,
                const float* __restrict__ m, const float* __restrict__ v)
{
    gemm_body<false>(w, x, g_qkv, RES, DIM,
                     (size_t)DIM * RES, (size_t)H_QKV * RES, g, b, m, v);
}

__global__ void __launch_bounds__(256, 2)
proj_gemm_kernel(const float* __restrict__ w, float* __restrict__ out,
                 const float* __restrict__ g, const float* __restrict__ b,
                 const float* __restrict__ m, const float* __restrict__ v)
{
    gemm_body<true>(w, g_av, out, RES, DH,
                    (size_t)DH * RES, (size_t)DIM * RES, g, b, m, v);
}

// =====================================================================
// Depthwise conv3 + BN on q channels.
// =====================================================================
__global__ void __launch_bounds__(256)
dwconv_kernel(const float* __restrict__ w_dw,
              const float* __restrict__ dg, const float* __restrict__ db,
              const float* __restrict__ dm, const float* __restrict__ dv)
{
    int bc = blockIdx.x;
    int b = bc >> 8, c = bc & 255;
    const float* in  = g_qkv + ((size_t)b * H_QKV + c) * RES;
    float*       out = g_q   + ((size_t)b * NH_KD + c) * RES;

    __shared__ float s[RES + 2];
    int tid = threadIdx.x;
    for (int i = tid; i < RES; i += 256) s[i + 1] = in[i];
    if (tid == 0) { s[0] = 0.0f; s[RES + 1] = 0.0f; }
    __syncthreads();

    float w0 = w_dw[c * 3 + 0], w1 = w_dw[c * 3 + 1], w2 = w_dw[c * 3 + 2];
    float inv  = dg[c] * rsqrtf(dv[c] + EPS);
    float beta = db[c] - dm[c] * inv;
    for (int i = tid; i < RES; i += 256) {
        float y = w0 * s[i] + w1 * s[i + 1] + w2 * s[i + 2];
        out[i] = y * inv + beta;
    }
}

// =====================================================================
// Fused scores + softmax (2-pass recompute).
// Pass 1: row max of (q.k*scale + bias) over all m.
// Pass 2: write exp(s - max) unnormalized, accumulate row sums -> g_rsum.
// Block: n-tile 128 rows, loops 8 m-tiles of 128. grid (8, 128 bh).
// =====================================================================
__global__ void __launch_bounds__(256, 2)
scores_softmax_kernel(const float* __restrict__ biases)
{
    int bh = blockIdx.y, b = bh >> 3, h = bh & 7;
    const float* Q  = g_q   + ((size_t)b * NH_KD + h * KEY_DIM) * RES;
    const float* Kp = g_qkv + ((size_t)b * H_QKV + NH_KD + h * KEY_DIM) * RES;
    float*       S  = g_attn + (size_t)bh * RES * RES;

    __shared__ float Qs[128 * 36];   // [n][d]
    __shared__ float Ks[32 * 136];   // [d][m]
    __shared__ float red[2 * 128];
    __shared__ float rmax[128];
    __shared__ float rsum[128];

    const int t = threadIdx.x;
    const int lane = t & 31, warp = t >> 5;
    const int wm = warp >> 1, wn = warp & 1;
    const int q_ = lane >> 2;
    const int n0 = blockIdx.x * 128;

    // Q tile load (transpose scatter) — once
#pragma unroll
    for (int i = 0; i < 4; i++) {
        int f = t + 256 * i;
        int d = f >> 5, c4 = (f & 31) * 4;
        float4 q = tf4(*(const float4*)(Q + (size_t)d * RES + n0 + c4));
        Qs[(c4 + 0) * 36 + d] = q.x;
        Qs[(c4 + 1) * 36 + d] = q.y;
        Qs[(c4 + 2) * 36 + d] = q.z;
        Qs[(c4 + 3) * 36 + d] = q.w;
    }
    if (t < 128) { rmax[t] = -1e30f; rsum[t] = 0.0f; }

    const float* brow = biases + h * RES;

    // ================= PASS 1: row max =================
    for (int mt = 0; mt < 8; mt++) {
        const int m0 = mt * 128;
        __syncthreads();
#pragma unroll
        for (int i = 0; i < 4; i++) {
            int f = t + 256 * i;
            int d = f >> 5, c4 = (f & 31) * 4;
            *(float4*)(Ks + d * 136 + c4) = tf4(*(const float4*)(Kp + (size_t)d * RES + m0 + c4));
        }
        __syncthreads();

        float acc[2][8][4];
#pragma unroll
        for (int a_ = 0; a_ < 2; a_++)
#pragma unroll
            for (int j = 0; j < 8; j++)
#pragma unroll
                for (int u = 0; u < 4; u++) acc[a_][j][u] = 0.0f;
#pragma unroll
        for (int s = 0; s < 4; s++)
            mma_step<36>(Qs, Ks, s, wm, wn, lane, acc);

        float pm[2][2] = {{-1e30f, -1e30f}, {-1e30f, -1e30f}};
#pragma unroll
        for (int a_ = 0; a_ < 2; a_++) {
            int nr0 = n0 + wm * 32 + a_ * 16 + q_;
            int nr1 = nr0 + 8;
#pragma unroll
            for (int j = 0; j < 8; j++) {
                int mc = m0 + wn * 64 + j * 8 + 2 * (lane & 3);
                float v0 = acc[a_][j][0] * SCALE_QK + __ldg(&brow[abs(nr0 - mc)]);
                float v1 = acc[a_][j][1] * SCALE_QK + __ldg(&brow[abs(nr0 - mc - 1)]);
                float v2 = acc[a_][j][2] * SCALE_QK + __ldg(&brow[abs(nr1 - mc)]);
                float v3 = acc[a_][j][3] * SCALE_QK + __ldg(&brow[abs(nr1 - mc - 1)]);
                pm[a_][0] = fmaxf(pm[a_][0], fmaxf(v0, v1));
                pm[a_][1] = fmaxf(pm[a_][1], fmaxf(v2, v3));
            }
        }
#pragma unroll
        for (int a_ = 0; a_ < 2; a_++)
#pragma unroll
            for (int hh = 0; hh < 2; hh++) {
                pm[a_][hh] = fmaxf(pm[a_][hh], __shfl_xor_sync(0xffffffffu, pm[a_][hh], 1));
                pm[a_][hh] = fmaxf(pm[a_][hh], __shfl_xor_sync(0xffffffffu, pm[a_][hh], 2));
            }
        if ((lane & 3) == 0) {
#pragma unroll
            for (int a_ = 0; a_ < 2; a_++) {
                red[wn * 128 + wm * 32 + a_ * 16 + q_]     = pm[a_][0];
                red[wn * 128 + wm * 32 + a_ * 16 + q_ + 8] = pm[a_][1];
            }
        }
        __syncthreads();
        if (t < 128) rmax[t] = fmaxf(rmax[t], fmaxf(red[t], red[t + 128]));
    }
    __syncthreads();

    // ================= PASS 2: exp + sum + store =================
    for (int mt = 0; mt < 8; mt++) {
        const int m0 = mt * 128;
        __syncthreads();
#pragma unroll
        for (int i = 0; i < 4; i++) {
            int f = t + 256 * i;
            int d = f >> 5, c4 = (f & 31) * 4;
            *(float4*)(Ks + d * 136 + c4) = tf4(*(const float4*)(Kp + (size_t)d * RES + m0 + c4));
        }
        __syncthreads();

        float acc[2][8][4];
#pragma unroll
        for (int a_ = 0; a_ < 2; a_++)
#pragma unroll
            for (int j = 0; j < 8; j++)
#pragma unroll
                for (int u = 0; u < 4; u++) acc[a_][j][u] = 0.0f;
#pragma unroll
        for (int s = 0; s < 4; s++)
            mma_step<36>(Qs, Ks, s, wm, wn, lane, acc);

        float ps[2][2] = {{0.f, 0.f}, {0.f, 0.f}};
#pragma unroll
        for (int a_ = 0; a_ < 2; a_++) {
            int r0l = wm * 32 + a_ * 16 + q_;
            int nr0 = n0 + r0l;
            int nr1 = nr0 + 8;
            float rm0 = rmax[r0l];
            float rm1 = rmax[r0l + 8];
#pragma unroll
            for (int j = 0; j < 8; j++) {
                int mc = m0 + wn * 64 + j * 8 + 2 * (lane & 3);
                float v0 = acc[a_][j][0] * SCALE_QK + __ldg(&brow[abs(nr0 - mc)]);
                float v1 = acc[a_][j][1] * SCALE_QK + __ldg(&brow[abs(nr0 - mc - 1)]);
                float v2 = acc[a_][j][2] * SCALE_QK + __ldg(&brow[abs(nr1 - mc)]);
                float v3 = acc[a_][j][3] * SCALE_QK + __ldg(&brow[abs(nr1 - mc - 1)]);
                float e0 = __expf(v0 - rm0);
                float e1 = __expf(v1 - rm0);
                float e2 = __expf(v2 - rm1);
                float e3 = __expf(v3 - rm1);
                ps[a_][0] += e0 + e1;
                ps[a_][1] += e2 + e3;
                *(float2*)&S[(size_t)nr0 * RES + mc] = make_float2(e0, e1);
                *(float2*)&S[(size_t)nr1 * RES + mc] = make_float2(e2, e3);
            }
        }
#pragma unroll
        for (int a_ = 0; a_ < 2; a_++)
#pragma unroll
            for (int hh = 0; hh < 2; hh++) {
                ps[a_][hh] += __shfl_xor_sync(0xffffffffu, ps[a_][hh], 1);
                ps[a_][hh] += __shfl_xor_sync(0xffffffffu, ps[a_][hh], 2);
            }
        if ((lane & 3) == 0) {
#pragma unroll
            for (int a_ = 0; a_ < 2; a_++) {
                red[wn * 128 + wm * 32 + a_ * 16 + q_]     = ps[a_][0];
                red[wn * 128 + wm * 32 + a_ * 16 + q_ + 8] = ps[a_][1];
            }
        }
        __syncthreads();
        if (t < 128) rsum[t] += red[t] + red[t + 128];
    }
    __syncthreads();
    if (t < 128) g_rsum[(size_t)bh * RES + n0 + t] = rsum[t];
}

// =====================================================================
// AV: O[d][n] = (sum_m V[d][m] * E[n][m]) / rsum[n]. 128x128, K=1024.
// =====================================================================
__global__ void __launch_bounds__(256, 2)
av_kernel()
{
    int bh = blockIdx.z, b = bh >> 3, h = bh & 7;
    const float* V = g_qkv + ((size_t)b * H_QKV + 2 * NH_KD + h * D_HEAD) * RES;
    const float* P = g_attn + (size_t)bh * RES * RES;
    float*       O = g_av  + ((size_t)b * DH + h * D_HEAD) * RES;

    __shared__ float As[2][128 * 20];
    __shared__ float Bs[2][16 * 136];

    const int t = threadIdx.x;
    const int lane = t & 31, warp = t >> 5;
    const int wm = warp >> 1, wn = warp & 1;
    const int n0 = blockIdx.x * 128;

    const int am  = t >> 1;
    const int akc = (t & 1) * 8;

    const float* Vptr = V + (size_t)am * RES + akc;
    const float* Pptr = P + (size_t)(n0 + am) * RES + akc;

    float acc[2][8][4];
#pragma unroll
    for (int a_ = 0; a_ < 2; a_++)
#pragma unroll
        for (int j = 0; j < 8; j++)
#pragma unroll
            for (int u = 0; u < 4; u++) acc[a_][j][u] = 0.0f;

    {
        float4 v0 = *(const float4*)(Vptr);
        float4 v1 = *(const float4*)(Vptr + 4);
        *(float4*)(As[0] + am * 20 + akc)     = tf4(v0);
        *(float4*)(As[0] + am * 20 + akc + 4) = tf4(v1);
        float4 p0 = tf4(*(const float4*)(Pptr));
        float4 p1 = tf4(*(const float4*)(Pptr + 4));
        Bs[0][(akc + 0) * 136 + am] = p0.x;
        Bs[0][(akc + 1) * 136 + am] = p0.y;
        Bs[0][(akc + 2) * 136 + am] = p0.z;
        Bs[0][(akc + 3) * 136 + am] = p0.w;
        Bs[0][(akc + 4) * 136 + am] = p1.x;
        Bs[0][(akc + 5) * 136 + am] = p1.y;
        Bs[0][(akc + 6) * 136 + am] = p1.z;
        Bs[0][(akc + 7) * 136 + am] = p1.w;
    }
    __syncthreads();

    int buf = 0;
    for (int m0 = 16; m0 < RES; m0 += 16) {
        float4 pv0 = *(const float4*)(Vptr + m0);
        float4 pv1 = *(const float4*)(Vptr + m0 + 4);
        float4 pp0 = *(const float4*)(Pptr + m0);
        float4 pp1 = *(const float4*)(Pptr + m0 + 4);

        mma_step<20>(As[buf], Bs[buf], 0, wm, wn, lane, acc);
        mma_step<20>(As[buf], Bs[buf], 1, wm, wn, lane, acc);

        int nb = buf ^ 1;
        *(float4*)(As[nb] + am * 20 + akc)     = tf4(pv0);
        *(float4*)(As[nb] + am * 20 + akc + 4) = tf4(pv1);
        pp0 = tf4(pp0); pp1 = tf4(pp1);
        Bs[nb][(akc + 0) * 136 + am] = pp0.x;
        Bs[nb][(akc + 1) * 136 + am] = pp0.y;
        Bs[nb][(akc + 2) * 136 + am] = pp0.z;
        Bs[nb][(akc + 3) * 136 + am] = pp0.w;
        Bs[nb][(akc + 4) * 136 + am] = pp1.x;
        Bs[nb][(akc + 5) * 136 + am] = pp1.y;
        Bs[nb][(akc + 6) * 136 + am] = pp1.z;
        Bs[nb][(akc + 7) * 136 + am] = pp1.w;
        __syncthreads();
        buf = nb;
    }
    mma_step<20>(As[buf], Bs[buf], 0, wm, wn, lane, acc);
    mma_step<20>(As[buf], Bs[buf], 1, wm, wn, lane, acc);

    // normalization factors per n-column
    const float* rs = g_rsum + (size_t)bh * RES + n0;
    float2 invj[8];
#pragma unroll
    for (int j = 0; j < 8; j++) {
        int col = wn * 64 + j * 8 + 2 * (lane & 3);
        float2 s = *(const float2*)&rs[col];
        invj[j] = make_float2(1.0f / s.x, 1.0f / s.y);
    }

#pragma unroll
    for (int a_ = 0; a_ < 2; a_++) {
        int r0 = wm * 32 + a_ * 16 + (lane >> 2);
        int r1 = r0 + 8;
#pragma unroll
        for (int j = 0; j < 8; j++) {
            int col = n0 + wn * 64 + j * 8 + 2 * (lane & 3);
            *(float2*)&O[(size_t)r0 * RES + col] =
                make_float2(acc[a_][j][0] * invj[j].x, acc[a_][j][1] * invj[j].y);
            *(float2*)&O[(size_t)r1 * RES + col] =
                make_float2(acc[a_][j][2] * invj[j].x, acc[a_][j][3] * invj[j].y);
        }
    }
}

// =====================================================================
extern "C" void kernel_launch(void* const* d_in, const int* in_sizes, int n_in,
                              void* d_out, int out_size)
{
    const float* x       = (const float*)d_in[0];
    const float* w_qkv   = (const float*)d_in[1];
    const float* qkv_g   = (const float*)d_in[2];
    const float* qkv_b   = (const float*)d_in[3];
    const float* qkv_m   = (const float*)d_in[4];
    const float* qkv_v   = (const float*)d_in[5];
    const float* w_dw    = (const float*)d_in[6];
    const float* dw_g    = (const float*)d_in[7];
    const float* dw_b    = (const float*)d_in[8];
    const float* dw_m    = (const float*)d_in[9];
    const float* dw_v    = (const float*)d_in[10];
    const float* w_proj  = (const float*)d_in[11];
    const float* proj_g  = (const float*)d_in[12];
    const float* proj_b  = (const float*)d_in[13];
    const float* proj_m  = (const float*)d_in[14];
    const float* proj_v  = (const float*)d_in[15];
    const float* biases  = (const float*)d_in[16];
    float* out = (float*)d_out;

    qkv_gemm_kernel<<<dim3(RES / 128, H_QKV / 128, B_SZ), 256>>>(x, w_qkv, qkv_g, qkv_b, qkv_m, qkv_v);
    dwconv_kernel<<<B_SZ * NH_KD, 256>>>(w_dw, dw_g, dw_b, dw_m, dw_v);
    scores_softmax_kernel<<<dim3(RES / 128, B_SZ * NUM_HEADS), 256>>>(biases);
    av_kernel<<<dim3(RES / 128, 1, B_SZ * NUM_HEADS), 256>>>();
    proj_gemm_kernel<<<dim3(RES / 128, DIM / 128, B_SZ), 256>>>(w_proj, out, proj_g, proj_b, proj_m, proj_v);
}

// round 12
// speedup vs baseline: 1.0005x; 1.0005x over previous
#include <cuda_runtime.h>
#include <math.h>

#define B_SZ      16
#define DIM       512
#define KEY_DIM   32
#define NUM_HEADS 8
#define RES       1024
#define NH_KD     256
#define D_HEAD    128
#define DH        1024
#define H_QKV     1536
#define EPS       1e-5f
#define SCALE_QK  0.17677669529663687f

// ---------------- static scratch ----------------
__device__ float g_qkv [B_SZ * H_QKV * RES];
__device__ float g_q   [B_SZ * NH_KD * RES];
__device__ float g_attn[134217728];           // 16*8*1024*1024 (unnormalized exp)
__device__ float g_av  [B_SZ * DH * RES];
__device__ float g_rsum[B_SZ * NUM_HEADS * RES];

// ---------------- tf32 helpers ----------------
__device__ __forceinline__ unsigned f2tf(float f) {
    unsigned r;
    asm("cvt.rna.tf32.f32 %0, %1;" : "=r"(r) : "f"(f));
    return r;
}
__device__ __forceinline__ float4 tf4(float4 v) {
    v.x = __uint_as_float(f2tf(v.x));
    v.y = __uint_as_float(f2tf(v.y));
    v.z = __uint_as_float(f2tf(v.z));
    v.w = __uint_as_float(f2tf(v.w));
    return v;
}
__device__ __forceinline__ void mma8(float c[4], const unsigned a[4],
                                     unsigned b0, unsigned b1) {
    asm("mma.sync.aligned.m16n8k8.row.col.f32.tf32.tf32.f32 "
        "{%0,%1,%2,%3},{%4,%5,%6,%7},{%8,%9},{%0,%1,%2,%3};"
        : "+f"(c[0]), "+f"(c[1]), "+f"(c[2]), "+f"(c[3])
        : "r"(a[0]), "r"(a[1]), "r"(a[2]), "r"(a[3]), "r"(b0), "r"(b1));
}

// ---------------- warp-tile mma step ----------------
// as: [m][k] stride AS; bs: [k][n] stride 136. One k8 step.
template<int AS>
__device__ __forceinline__ void mma_step(const float* __restrict__ as,
                                         const float* __restrict__ bs,
                                         int s, int wm, int wn, int lane,
                                         float acc[2][8][4])
{
    unsigned afr[2][4];
    const int kk = s * 8 + (lane & 3);
#pragma unroll
    for (int a_ = 0; a_ < 2; a_++) {
        int mr = wm * 32 + a_ * 16 + (lane >> 2);
        afr[a_][0] = __float_as_uint(as[mr * AS + kk]);
        afr[a_][1] = __float_as_uint(as[(mr + 8) * AS + kk]);
        afr[a_][2] = __float_as_uint(as[mr * AS + kk + 4]);
        afr[a_][3] = __float_as_uint(as[(mr + 8) * AS + kk + 4]);
    }
#pragma unroll
    for (int j = 0; j < 8; j++) {
        int col = wn * 64 + j * 8 + (lane >> 2);
        unsigned b0 = __float_as_uint(bs[(s * 8 + (lane & 3)) * 136 + col]);
        unsigned b1 = __float_as_uint(bs[(s * 8 + (lane & 3) + 4) * 136 + col]);
        mma8(acc[0][j], afr[0], b0, b1);
        mma8(acc[1][j], afr[1], b0, b1);
    }
}

// =====================================================================
// Channel GEMM+BN: 128x128 tile, double-buffered tf32 mma.
// =====================================================================
template<bool RELU_B>
__device__ __forceinline__ void gemm_body(
    const float* __restrict__ A, const float* __restrict__ Bm, float* __restrict__ C,
    int N, int K, size_t sB, size_t sC,
    const float* __restrict__ gg, const float* __restrict__ bbp,
    const float* __restrict__ mmp, const float* __restrict__ vvp)
{
    __shared__ float As[2][128 * 20];
    __shared__ float Bs[2][16 * 136];
    const float* Bb = Bm + (size_t)blockIdx.z * sB;
    float*       Cb = C  + (size_t)blockIdx.z * sC;

    const int t = threadIdx.x;
    const int lane = t & 31, warp = t >> 5;
    const int wm = warp >> 1, wn = warp & 1;
    const int row0 = blockIdx.y * 128, col0 = blockIdx.x * 128;

    const int am  = t >> 1;
    const int akc = (t & 1) * 8;
    const int bkr = t >> 5;
    const int bc4 = (t & 31) * 4;

    const float* Aptr  = A  + (size_t)(row0 + am) * K + akc;
    const float* Bptr0 = Bb + (size_t)bkr * N + col0 + bc4;
    const float* Bptr1 = Bb + (size_t)(bkr + 8) * N + col0 + bc4;

    float acc[2][8][4];
#pragma unroll
    for (int a_ = 0; a_ < 2; a_++)
#pragma unroll
        for (int j = 0; j < 8; j++)
#pragma unroll
            for (int u = 0; u < 4; u++) acc[a_][j][u] = 0.0f;

    {
        float4 a0 = *(const float4*)(Aptr);
        float4 a1 = *(const float4*)(Aptr + 4);
        *(float4*)(As[0] + am * 20 + akc)     = tf4(a0);
        *(float4*)(As[0] + am * 20 + akc + 4) = tf4(a1);
        float4 b0 = *(const float4*)(Bptr0);
        float4 b1 = *(const float4*)(Bptr1);
        if (RELU_B) {
            b0.x = fmaxf(b0.x, 0.f); b0.y = fmaxf(b0.y, 0.f); b0.z = fmaxf(b0.z, 0.f); b0.w = fmaxf(b0.w, 0.f);
            b1.x = fmaxf(b1.x, 0.f); b1.y = fmaxf(b1.y, 0.f); b1.z = fmaxf(b1.z, 0.f); b1.w = fmaxf(b1.w, 0.f);
        }
        *(float4*)(Bs[0] + bkr * 136 + bc4)       = tf4(b0);
        *(float4*)(Bs[0] + (bkr + 8) * 136 + bc4) = tf4(b1);
    }
    __syncthreads();

    int buf = 0;
    for (int k0 = 16; k0 < K; k0 += 16) {
        float4 pa0 = *(const float4*)(Aptr + k0);
        float4 pa1 = *(const float4*)(Aptr + k0 + 4);
        float4 pb0 = *(const float4*)(Bptr0 + (size_t)k0 * N);
        float4 pb1 = *(const float4*)(Bptr1 + (size_t)k0 * N);

        mma_step<20>(As[buf], Bs[buf], 0, wm, wn, lane, acc);
        mma_step<20>(As[buf], Bs[buf], 1, wm, wn, lane, acc);

        if (RELU_B) {
            pb0.x = fmaxf(pb0.x, 0.f); pb0.y = fmaxf(pb0.y, 0.f); pb0.z = fmaxf(pb0.z, 0.f); pb0.w = fmaxf(pb0.w, 0.f);
            pb1.x = fmaxf(pb1.x, 0.f); pb1.y = fmaxf(pb1.y, 0.f); pb1.z = fmaxf(pb1.z, 0.f); pb1.w = fmaxf(pb1.w, 0.f);
        }
        int nb = buf ^ 1;
        *(float4*)(As[nb] + am * 20 + akc)        = tf4(pa0);
        *(float4*)(As[nb] + am * 20 + akc + 4)    = tf4(pa1);
        *(float4*)(Bs[nb] + bkr * 136 + bc4)      = tf4(pb0);
        *(float4*)(Bs[nb] + (bkr + 8) * 136 + bc4)= tf4(pb1);
        __syncthreads();
        buf = nb;
    }
    mma_step<20>(As[buf], Bs[buf], 0, wm, wn, lane, acc);
    mma_step<20>(As[buf], Bs[buf], 1, wm, wn, lane, acc);

#pragma unroll
    for (int a_ = 0; a_ < 2; a_++) {
        int r0 = row0 + wm * 32 + a_ * 16 + (lane >> 2);
        int r1 = r0 + 8;
        float inv0  = gg[r0] * rsqrtf(vvp[r0] + EPS);
        float beta0 = bbp[r0] - mmp[r0] * inv0;
        float inv1  = gg[r1] * rsqrtf(vvp[r1] + EPS);
        float beta1 = bbp[r1] - mmp[r1] * inv1;
#pragma unroll
        for (int j = 0; j < 8; j++) {
            int col = col0 + wn * 64 + j * 8 + 2 * (lane & 3);
            float2 w0 = make_float2(acc[a_][j][0] * inv0 + beta0,
                                    acc[a_][j][1] * inv0 + beta0);
            float2 w1 = make_float2(acc[a_][j][2] * inv1 + beta1,
                                    acc[a_][j][3] * inv1 + beta1);
            *(float2*)&Cb[(size_t)r0 * N + col] = w0;
            *(float2*)&Cb[(size_t)r1 * N + col] = w1;
        }
    }
}

__global__ void __launch_bounds__(256, 2)
qkv_gemm_kernel(const float* __restrict__ x, const float* __restrict__ w,
                const float* __restrict__ g, const float* __restrict__ b,
                const float* __restrict__ m, const float* __restrict__ v)
{
    gemm_body<false>(w, x, g_qkv, RES, DIM,
                     (size_t)DIM * RES, (size_t)H_QKV * RES, g, b, m, v);
}

__global__ void __launch_bounds__(256, 2)
proj_gemm_kernel(const float* __restrict__ w, float* __restrict__ out,
                 const float* __restrict__ g, const float* __restrict__ b,
                 const float* __restrict__ m, const float* __restrict__ v)
{
    gemm_body<true>(w, g_av, out, RES, DH,
                    (size_t)DH * RES, (size_t)DIM * RES, g, b, m, v);
}

// =====================================================================
// Depthwise conv3 + BN on q channels.
// =====================================================================
__global__ void __launch_bounds__(256)
dwconv_kernel(const float* __restrict__ w_dw,
              const float* __restrict__ dg, const float* __restrict__ db,
              const float* __restrict__ dm, const float* __restrict__ dv)
{
    int bc = blockIdx.x;
    int b = bc >> 8, c = bc & 255;
    const float* in  = g_qkv + ((size_t)b * H_QKV + c) * RES;
    float*       out = g_q   + ((size_t)b * NH_KD + c) * RES;

    __shared__ float s[RES + 2];
    int tid = threadIdx.x;
    for (int i = tid; i < RES; i += 256) s[i + 1] = in[i];
    if (tid == 0) { s[0] = 0.0f; s[RES + 1] = 0.0f; }
    __syncthreads();

    float w0 = w_dw[c * 3 + 0], w1 = w_dw[c * 3 + 1], w2 = w_dw[c * 3 + 2];
    float inv  = dg[c] * rsqrtf(dv[c] + EPS);
    float beta = db[c] - dm[c] * inv;
    for (int i = tid; i < RES; i += 256) {
        float y = w0 * s[i] + w1 * s[i + 1] + w2 * s[i + 2];
        out[i] = y * inv + beta;
    }
}

// =====================================================================
// Fused scores + softmax (2-pass recompute).
// Pass 1: row max of (q.k*scale + bias) over all m.
// Pass 2: write exp(s - max) unnormalized, accumulate row sums -> g_rsum.
// Block: n-tile 128 rows, loops 8 m-tiles of 128. grid (8, 128 bh).
// =====================================================================
__global__ void __launch_bounds__(256, 2)
scores_softmax_kernel(const float* __restrict__ biases)
{
    int bh = blockIdx.y, b = bh >> 3, h = bh & 7;
    const float* Q  = g_q   + ((size_t)b * NH_KD + h * KEY_DIM) * RES;
    const float* Kp = g_qkv + ((size_t)b * H_QKV + NH_KD + h * KEY_DIM) * RES;
    float*       S  = g_attn + (size_t)bh * RES * RES;

    __shared__ float Qs[128 * 36];   // [n][d]
    __shared__ float Ks[32 * 136];   // [d][m]
    __shared__ float red[2 * 128];
    __shared__ float rmax[128];
    __shared__ float rsum[128];

    const int t = threadIdx.x;
    const int lane = t & 31, warp = t >> 5;
    const int wm = warp >> 1, wn = warp & 1;
    const int q_ = lane >> 2;
    const int n0 = blockIdx.x * 128;

    // Q tile load (transpose scatter) — once
#pragma unroll
    for (int i = 0; i < 4; i++) {
        int f = t + 256 * i;
        int d = f >> 5, c4 = (f & 31) * 4;
        float4 q = tf4(*(const float4*)(Q + (size_t)d * RES + n0 + c4));
        Qs[(c4 + 0) * 36 + d] = q.x;
        Qs[(c4 + 1) * 36 + d] = q.y;
        Qs[(c4 + 2) * 36 + d] = q.z;
        Qs[(c4 + 3) * 36 + d] = q.w;
    }
    if (t < 128) { rmax[t] = -1e30f; rsum[t] = 0.0f; }

    const float* brow = biases + h * RES;

    // ================= PASS 1: row max =================
    for (int mt = 0; mt < 8; mt++) {
        const int m0 = mt * 128;
        __syncthreads();
#pragma unroll
        for (int i = 0; i < 4; i++) {
            int f = t + 256 * i;
            int d = f >> 5, c4 = (f & 31) * 4;
            *(float4*)(Ks + d * 136 + c4) = tf4(*(const float4*)(Kp + (size_t)d * RES + m0 + c4));
        }
        __syncthreads();

        float acc[2][8][4];
#pragma unroll
        for (int a_ = 0; a_ < 2; a_++)
#pragma unroll
            for (int j = 0; j < 8; j++)
#pragma unroll
                for (int u = 0; u < 4; u++) acc[a_][j][u] = 0.0f;
#pragma unroll
        for (int s = 0; s < 4; s++)
            mma_step<36>(Qs, Ks, s, wm, wn, lane, acc);

        float pm[2][2] = {{-1e30f, -1e30f}, {-1e30f, -1e30f}};
#pragma unroll
        for (int a_ = 0; a_ < 2; a_++) {
            int nr0 = n0 + wm * 32 + a_ * 16 + q_;
            int nr1 = nr0 + 8;
#pragma unroll
            for (int j = 0; j < 8; j++) {
                int mc = m0 + wn * 64 + j * 8 + 2 * (lane & 3);
                float v0 = acc[a_][j][0] * SCALE_QK + __ldg(&brow[abs(nr0 - mc)]);
                float v1 = acc[a_][j][1] * SCALE_QK + __ldg(&brow[abs(nr0 - mc - 1)]);
                float v2 = acc[a_][j][2] * SCALE_QK + __ldg(&brow[abs(nr1 - mc)]);
                float v3 = acc[a_][j][3] * SCALE_QK + __ldg(&brow[abs(nr1 - mc - 1)]);
                pm[a_][0] = fmaxf(pm[a_][0], fmaxf(v0, v1));
                pm[a_][1] = fmaxf(pm[a_][1], fmaxf(v2, v3));
            }
        }
#pragma unroll
        for (int a_ = 0; a_ < 2; a_++)
#pragma unroll
            for (int hh = 0; hh < 2; hh++) {
                pm[a_][hh] = fmaxf(pm[a_][hh], __shfl_xor_sync(0xffffffffu, pm[a_][hh], 1));
                pm[a_][hh] = fmaxf(pm[a_][hh], __shfl_xor_sync(0xffffffffu, pm[a_][hh], 2));
            }
        if ((lane & 3) == 0) {
#pragma unroll
            for (int a_ = 0; a_ < 2; a_++) {
                red[wn * 128 + wm * 32 + a_ * 16 + q_]     = pm[a_][0];
                red[wn * 128 + wm * 32 + a_ * 16 + q_ + 8] = pm[a_][1];
            }
        }
        __syncthreads();
        if (t < 128) rmax[t] = fmaxf(rmax[t], fmaxf(red[t], red[t + 128]));
    }
    __syncthreads();

    // ================= PASS 2: exp + sum + store =================
    for (int mt = 0; mt < 8; mt++) {
        const int m0 = mt * 128;
        __syncthreads();
#pragma unroll
        for (int i = 0; i < 4; i++) {
            int f = t + 256 * i;
            int d = f >> 5, c4 = (f & 31) * 4;
            *(float4*)(Ks + d * 136 + c4) = tf4(*(const float4*)(Kp + (size_t)d * RES + m0 + c4));
        }
        __syncthreads();

        float acc[2][8][4];
#pragma unroll
        for (int a_ = 0; a_ < 2; a_++)
#pragma unroll
            for (int j = 0; j < 8; j++)
#pragma unroll
                for (int u = 0; u < 4; u++) acc[a_][j][u] = 0.0f;
#pragma unroll
        for (int s = 0; s < 4; s++)
            mma_step<36>(Qs, Ks, s, wm, wn, lane, acc);

        float ps[2][2] = {{0.f, 0.f}, {0.f, 0.f}};
#pragma unroll
        for (int a_ = 0; a_ < 2; a_++) {
            int r0l = wm * 32 + a_ * 16 + q_;
            int nr0 = n0 + r0l;
            int nr1 = nr0 + 8;
            float rm0 = rmax[r0l];
            float rm1 = rmax[r0l + 8];
#pragma unroll
            for (int j = 0; j < 8; j++) {
                int mc = m0 + wn * 64 + j * 8 + 2 * (lane & 3);
                float v0 = acc[a_][j][0] * SCALE_QK + __ldg(&brow[abs(nr0 - mc)]);
                float v1 = acc[a_][j][1] * SCALE_QK + __ldg(&brow[abs(nr0 - mc - 1)]);
                float v2 = acc[a_][j][2] * SCALE_QK + __ldg(&brow[abs(nr1 - mc)]);
                float v3 = acc[a_][j][3] * SCALE_QK + __ldg(&brow[abs(nr1 - mc - 1)]);
                float e0 = __expf(v0 - rm0);
                float e1 = __expf(v1 - rm0);
                float e2 = __expf(v2 - rm1);
                float e3 = __expf(v3 - rm1);
                ps[a_][0] += e0 + e1;
                ps[a_][1] += e2 + e3;
                *(float2*)&S[(size_t)nr0 * RES + mc] = make_float2(e0, e1);
                *(float2*)&S[(size_t)nr1 * RES + mc] = make_float2(e2, e3);
            }
        }
#pragma unroll
        for (int a_ = 0; a_ < 2; a_++)
#pragma unroll
            for (int hh = 0; hh < 2; hh++) {
                ps[a_][hh] += __shfl_xor_sync(0xffffffffu, ps[a_][hh], 1);
                ps[a_][hh] += __shfl_xor_sync(0xffffffffu, ps[a_][hh], 2);
            }
        if ((lane & 3) == 0) {
#pragma unroll
            for (int a_ = 0; a_ < 2; a_++) {
                red[wn * 128 + wm * 32 + a_ * 16 + q_]     = ps[a_][0];
                red[wn * 128 + wm * 32 + a_ * 16 + q_ + 8] = ps[a_][1];
            }
        }
        __syncthreads();
        if (t < 128) rsum[t] += red[t] + red[t + 128];
    }
    __syncthreads();
    if (t < 128) g_rsum[(size_t)bh * RES + n0 + t] = rsum[t];
}

// =====================================================================
// AV: O[d][n] = (sum_m V[d][m] * E[n][m]) / rsum[n]. 128x128, K=1024.
// =====================================================================
__global__ void __launch_bounds__(256, 2)
av_kernel()
{
    int bh = blockIdx.z, b = bh >> 3, h = bh & 7;
    const float* V = g_qkv + ((size_t)b * H_QKV + 2 * NH_KD + h * D_HEAD) * RES;
    const float* P = g_attn + (size_t)bh * RES * RES;
    float*       O = g_av  + ((size_t)b * DH + h * D_HEAD) * RES;

    __shared__ float As[2][128 * 20];
    __shared__ float Bs[2][16 * 136];

    const int t = threadIdx.x;
    const int lane = t & 31, warp = t >> 5;
    const int wm = warp >> 1, wn = warp & 1;
    const int n0 = blockIdx.x * 128;

    const int am  = t >> 1;
    const int akc = (t & 1) * 8;

    const float* Vptr = V + (size_t)am * RES + akc;
    const float* Pptr = P + (size_t)(n0 + am) * RES + akc;

    float acc[2][8][4];
#pragma unroll
    for (int a_ = 0; a_ < 2; a_++)
#pragma unroll
        for (int j = 0; j < 8; j++)
#pragma unroll
            for (int u = 0; u < 4; u++) acc[a_][j][u] = 0.0f;

    {
        float4 v0 = *(const float4*)(Vptr);
        float4 v1 = *(const float4*)(Vptr + 4);
        *(float4*)(As[0] + am * 20 + akc)     = tf4(v0);
        *(float4*)(As[0] + am * 20 + akc + 4) = tf4(v1);
        float4 p0 = tf4(*(const float4*)(Pptr));
        float4 p1 = tf4(*(const float4*)(Pptr + 4));
        Bs[0][(akc + 0) * 136 + am] = p0.x;
        Bs[0][(akc + 1) * 136 + am] = p0.y;
        Bs[0][(akc + 2) * 136 + am] = p0.z;
        Bs[0][(akc + 3) * 136 + am] = p0.w;
        Bs[0][(akc + 4) * 136 + am] = p1.x;
        Bs[0][(akc + 5) * 136 + am] = p1.y;
        Bs[0][(akc + 6) * 136 + am] = p1.z;
        Bs[0][(akc + 7) * 136 + am] = p1.w;
    }
    __syncthreads();

    int buf = 0;
    for (int m0 = 16; m0 < RES; m0 += 16) {
        float4 pv0 = *(const float4*)(Vptr + m0);
        float4 pv1 = *(const float4*)(Vptr + m0 + 4);
        float4 pp0 = *(const float4*)(Pptr + m0);
        float4 pp1 = *(const float4*)(Pptr + m0 + 4);

        mma_step<20>(As[buf], Bs[buf], 0, wm, wn, lane, acc);
        mma_step<20>(As[buf], Bs[buf], 1, wm, wn, lane, acc);

        int nb = buf ^ 1;
        *(float4*)(As[nb] + am * 20 + akc)     = tf4(pv0);
        *(float4*)(As[nb] + am * 20 + akc + 4) = tf4(pv1);
        pp0 = tf4(pp0); pp1 = tf4(pp1);
        Bs[nb][(akc + 0) * 136 + am] = pp0.x;
        Bs[nb][(akc + 1) * 136 + am] = pp0.y;
        Bs[nb][(akc + 2) * 136 + am] = pp0.z;
        Bs[nb][(akc + 3) * 136 + am] = pp0.w;
        Bs[nb][(akc + 4) * 136 + am] = pp1.x;
        Bs[nb][(akc + 5) * 136 + am] = pp1.y;
        Bs[nb][(akc + 6) * 136 + am] = pp1.z;
        Bs[nb][(akc + 7) * 136 + am] = pp1.w;
        __syncthreads();
        buf = nb;
    }
    mma_step<20>(As[buf], Bs[buf], 0, wm, wn, lane, acc);
    mma_step<20>(As[buf], Bs[buf], 1, wm, wn, lane, acc);

    // normalization factors per n-column
    const float* rs = g_rsum + (size_t)bh * RES + n0;
    float2 invj[8];
#pragma unroll
    for (int j = 0; j < 8; j++) {
        int col = wn * 64 + j * 8 + 2 * (lane & 3);
        float2 s = *(const float2*)&rs[col];
        invj[j] = make_float2(1.0f / s.x, 1.0f / s.y);
    }

#pragma unroll
    for (int a_ = 0; a_ < 2; a_++) {
        int r0 = wm * 32 + a_ * 16 + (lane >> 2);
        int r1 = r0 + 8;
#pragma unroll
        for (int j = 0; j < 8; j++) {
            int col = n0 + wn * 64 + j * 8 + 2 * (lane & 3);
            *(float2*)&O[(size_t)r0 * RES + col] =
                make_float2(acc[a_][j][0] * invj[j].x, acc[a_][j][1] * invj[j].y);
            *(float2*)&O[(size_t)r1 * RES + col] =
                make_float2(acc[a_][j][2] * invj[j].x, acc[a_][j][3] * invj[j].y);
        }
    }
}

// =====================================================================
extern "C" void kernel_launch(void* const* d_in, const int* in_sizes, int n_in,
                              void* d_out, int out_size)
{
    const float* x       = (const float*)d_in[0];
    const float* w_qkv   = (const float*)d_in[1];
    const float* qkv_g   = (const float*)d_in[2];
    const float* qkv_b   = (const float*)d_in[3];
    const float* qkv_m   = (const float*)d_in[4];
    const float* qkv_v   = (const float*)d_in[5];
    const float* w_dw    = (const float*)d_in[6];
    const float* dw_g    = (const float*)d_in[7];
    const float* dw_b    = (const float*)d_in[8];
    const float* dw_m    = (const float*)d_in[9];
    const float* dw_v    = (const float*)d_in[10];
    const float* w_proj  = (const float*)d_in[11];
    const float* proj_g  = (const float*)d_in[12];
    const float* proj_b  = (const float*)d_in[13];
    const float* proj_m  = (const float*)d_in[14];
    const float* proj_v  = (const float*)d_in[15];
    const float* biases  = (const float*)d_in[16];
    float* out = (float*)d_out;

    qkv_gemm_kernel<<<dim3(RES / 128, H_QKV / 128, B_SZ), 256>>>(x, w_qkv, qkv_g, qkv_b, qkv_m, qkv_v);
    dwconv_kernel<<<B_SZ * NH_KD, 256>>>(w_dw, dw_g, dw_b, dw_m, dw_v);
    scores_softmax_kernel<<<dim3(RES / 128, B_SZ * NUM_HEADS), 256>>>(biases);
    av_kernel<<<dim3(RES / 128, 1, B_SZ * NUM_HEADS), 256>>>();
    proj_gemm_kernel<<<dim3(RES / 128, DIM / 128, B_SZ), 256>>>(w_proj, out, proj_g, proj_b, proj_m, proj_v);
}

// round 13
// speedup vs baseline: 1.0013x; 1.0008x over previous
#include <cuda_runtime.h>
#include <math.h>

#define B_SZ      16
#define DIM       512
#define KEY_DIM   32
#define NUM_HEADS 8
#define RES       1024
#define NH_KD     256
#define D_HEAD    128
#define DH        1024
#define H_QKV     1536
#define EPS       1e-5f
#define SCALE_QK  0.17677669529663687f

// ---------------- static scratch ----------------
__device__ float g_qkv [B_SZ * H_QKV * RES];
__device__ float g_q   [B_SZ * NH_KD * RES];
__device__ float g_attn[134217728];           // 16*8*1024*1024 (unnormalized exp)
__device__ float g_av  [B_SZ * DH * RES];
__device__ float g_rsum[B_SZ * NUM_HEADS * RES];

// ---------------- tf32 helpers ----------------
__device__ __forceinline__ unsigned f2tf(float f) {
    unsigned r;
    asm("cvt.rna.tf32.f32 %0, %1;" : "=r"(r) : "f"(f));
    return r;
}
__device__ __forceinline__ float4 tf4(float4 v) {
    v.x = __uint_as_float(f2tf(v.x));
    v.y = __uint_as_float(f2tf(v.y));
    v.z = __uint_as_float(f2tf(v.z));
    v.w = __uint_as_float(f2tf(v.w));
    return v;
}
__device__ __forceinline__ void mma8(float c[4], const unsigned a[4],
                                     unsigned b0, unsigned b1) {
    asm("mma.sync.aligned.m16n8k8.row.col.f32.tf32.tf32.f32 "
        "{%0,%1,%2,%3},{%4,%5,%6,%7},{%8,%9},{%0,%1,%2,%3};"
        : "+f"(c[0]), "+f"(c[1]), "+f"(c[2]), "+f"(c[3])
        : "r"(a[0]), "r"(a[1]), "r"(a[2]), "r"(a[3]), "r"(b0), "r"(b1));
}

// ---------------- warp-tile mma step ----------------
// as: [m][k] stride AS; bs: [k][n] stride 136. One k8 step.
template<int AS>
__device__ __forceinline__ void mma_step(const float* __restrict__ as,
                                         const float* __restrict__ bs,
                                         int s, int wm, int wn, int lane,
                                         float acc[2][8][4])
{
    unsigned afr[2][4];
    const int kk = s * 8 + (lane & 3);
#pragma unroll
    for (int a_ = 0; a_ < 2; a_++) {
        int mr = wm * 32 + a_ * 16 + (lane >> 2);
        afr[a_][0] = __float_as_uint(as[mr * AS + kk]);
        afr[a_][1] = __float_as_uint(as[(mr + 8) * AS + kk]);
        afr[a_][2] = __float_as_uint(as[mr * AS + kk + 4]);
        afr[a_][3] = __float_as_uint(as[(mr + 8) * AS + kk + 4]);
    }
#pragma unroll
    for (int j = 0; j < 8; j++) {
        int col = wn * 64 + j * 8 + (lane >> 2);
        unsigned b0 = __float_as_uint(bs[(s * 8 + (lane & 3)) * 136 + col]);
        unsigned b1 = __float_as_uint(bs[(s * 8 + (lane & 3) + 4) * 136 + col]);
        mma8(acc[0][j], afr[0], b0, b1);
        mma8(acc[1][j], afr[1], b0, b1);
    }
}

// =====================================================================
// Channel GEMM+BN: 128x128 tile, double-buffered tf32 mma.
// =====================================================================
template<bool RELU_B>
__device__ __forceinline__ void gemm_body(
    const float* __restrict__ A, const float* __restrict__ Bm, float* __restrict__ C,
    int N, int K, size_t sB, size_t sC,
    const float* __restrict__ gg, const float* __restrict__ bbp,
    const float* __restrict__ mmp, const float* __restrict__ vvp)
{
    __shared__ float As[2][128 * 20];
    __shared__ float Bs[2][16 * 136];
    const float* Bb = Bm + (size_t)blockIdx.z * sB;
    float*       Cb = C  + (size_t)blockIdx.z * sC;

    const int t = threadIdx.x;
    const int lane = t & 31, warp = t >> 5;
    const int wm = warp >> 1, wn = warp & 1;
    const int row0 = blockIdx.y * 128, col0 = blockIdx.x * 128;

    const int am  = t >> 1;
    const int akc = (t & 1) * 8;
    const int bkr = t >> 5;
    const int bc4 = (t & 31) * 4;

    const float* Aptr  = A  + (size_t)(row0 + am) * K + akc;
    const float* Bptr0 = Bb + (size_t)bkr * N + col0 + bc4;
    const float* Bptr1 = Bb + (size_t)(bkr + 8) * N + col0 + bc4;

    float acc[2][8][4];
#pragma unroll
    for (int a_ = 0; a_ < 2; a_++)
#pragma unroll
        for (int j = 0; j < 8; j++)
#pragma unroll
            for (int u = 0; u < 4; u++) acc[a_][j][u] = 0.0f;

    {
        float4 a0 = *(const float4*)(Aptr);
        float4 a1 = *(const float4*)(Aptr + 4);
        *(float4*)(As[0] + am * 20 + akc)     = tf4(a0);
        *(float4*)(As[0] + am * 20 + akc + 4) = tf4(a1);
        float4 b0 = *(const float4*)(Bptr0);
        float4 b1 = *(const float4*)(Bptr1);
        if (RELU_B) {
            b0.x = fmaxf(b0.x, 0.f); b0.y = fmaxf(b0.y, 0.f); b0.z = fmaxf(b0.z, 0.f); b0.w = fmaxf(b0.w, 0.f);
            b1.x = fmaxf(b1.x, 0.f); b1.y = fmaxf(b1.y, 0.f); b1.z = fmaxf(b1.z, 0.f); b1.w = fmaxf(b1.w, 0.f);
        }
        *(float4*)(Bs[0] + bkr * 136 + bc4)       = tf4(b0);
        *(float4*)(Bs[0] + (bkr + 8) * 136 + bc4) = tf4(b1);
    }
    __syncthreads();

    int buf = 0;
    for (int k0 = 16; k0 < K; k0 += 16) {
        float4 pa0 = *(const float4*)(Aptr + k0);
        float4 pa1 = *(const float4*)(Aptr + k0 + 4);
        float4 pb0 = *(const float4*)(Bptr0 + (size_t)k0 * N);
        float4 pb1 = *(const float4*)(Bptr1 + (size_t)k0 * N);

        mma_step<20>(As[buf], Bs[buf], 0, wm, wn, lane, acc);
        mma_step<20>(As[buf], Bs[buf], 1, wm, wn, lane, acc);

        if (RELU_B) {
            pb0.x = fmaxf(pb0.x, 0.f); pb0.y = fmaxf(pb0.y, 0.f); pb0.z = fmaxf(pb0.z, 0.f); pb0.w = fmaxf(pb0.w, 0.f);
            pb1.x = fmaxf(pb1.x, 0.f); pb1.y = fmaxf(pb1.y, 0.f); pb1.z = fmaxf(pb1.z, 0.f); pb1.w = fmaxf(pb1.w, 0.f);
        }
        int nb = buf ^ 1;
        *(float4*)(As[nb] + am * 20 + akc)        = tf4(pa0);
        *(float4*)(As[nb] + am * 20 + akc + 4)    = tf4(pa1);
        *(float4*)(Bs[nb] + bkr * 136 + bc4)      = tf4(pb0);
        *(float4*)(Bs[nb] + (bkr + 8) * 136 + bc4)= tf4(pb1);
        __syncthreads();
        buf = nb;
    }
    mma_step<20>(As[buf], Bs[buf], 0, wm, wn, lane, acc);
    mma_step<20>(As[buf], Bs[buf], 1, wm, wn, lane, acc);

#pragma unroll
    for (int a_ = 0; a_ < 2; a_++) {
        int r0 = row0 + wm * 32 + a_ * 16 + (lane >> 2);
        int r1 = r0 + 8;
        float inv0  = gg[r0] * rsqrtf(vvp[r0] + EPS);
        float beta0 = bbp[r0] - mmp[r0] * inv0;
        float inv1  = gg[r1] * rsqrtf(vvp[r1] + EPS);
        float beta1 = bbp[r1] - mmp[r1] * inv1;
#pragma unroll
        for (int j = 0; j < 8; j++) {
            int col = col0 + wn * 64 + j * 8 + 2 * (lane & 3);
            float2 w0 = make_float2(acc[a_][j][0] * inv0 + beta0,
                                    acc[a_][j][1] * inv0 + beta0);
            float2 w1 = make_float2(acc[a_][j][2] * inv1 + beta1,
                                    acc[a_][j][3] * inv1 + beta1);
            *(float2*)&Cb[(size_t)r0 * N + col] = w0;
            *(float2*)&Cb[(size_t)r1 * N + col] = w1;
        }
    }
}

__global__ void __launch_bounds__(256, 2)
qkv_gemm_kernel(const float* __restrict__ x, const float* __restrict__ w,
                const float* __restrict__ g, const float* __restrict__ b,
                const float* __restrict__ m, const float* __restrict__ v)
{
    gemm_body<false>(w, x, g_qkv, RES, DIM,
                     (size_t)DIM * RES, (size_t)H_QKV * RES, g, b, m, v);
}

__global__ void __launch_bounds__(256, 2)
proj_gemm_kernel(const float* __restrict__ w, float* __restrict__ out,
                 const float* __restrict__ g, const float* __restrict__ b,
                 const float* __restrict__ m, const float* __restrict__ v)
{
    gemm_body<true>(w, g_av, out, RES, DH,
                    (size_t)DH * RES, (size_t)DIM * RES, g, b, m, v);
}

// =====================================================================
// Depthwise conv3 + BN on q channels.
// =====================================================================
__global__ void __launch_bounds__(256)
dwconv_kernel(const float* __restrict__ w_dw,
              const float* __restrict__ dg, const float* __restrict__ db,
              const float* __restrict__ dm, const float* __restrict__ dv)
{
    int bc = blockIdx.x;
    int b = bc >> 8, c = bc & 255;
    const float* in  = g_qkv + ((size_t)b * H_QKV + c) * RES;
    float*       out = g_q   + ((size_t)b * NH_KD + c) * RES;

    __shared__ float s[RES + 2];
    int tid = threadIdx.x;
    for (int i = tid; i < RES; i += 256) s[i + 1] = in[i];
    if (tid == 0) { s[0] = 0.0f; s[RES + 1] = 0.0f; }
    __syncthreads();

    float w0 = w_dw[c * 3 + 0], w1 = w_dw[c * 3 + 1], w2 = w_dw[c * 3 + 2];
    float inv  = dg[c] * rsqrtf(dv[c] + EPS);
    float beta = db[c] - dm[c] * inv;
    for (int i = tid; i < RES; i += 256) {
        float y = w0 * s[i] + w1 * s[i + 1] + w2 * s[i + 2];
        out[i] = y * inv + beta;
    }
}

// =====================================================================
// Fused scores + softmax (2-pass recompute).
// Pass 1: row max of (q.k*scale + bias) over all m.
// Pass 2: write exp(s - max) unnormalized, accumulate row sums -> g_rsum.
// Block: n-tile 128 rows, loops 8 m-tiles of 128. grid (8, 128 bh).
// =====================================================================
__global__ void __launch_bounds__(256, 2)
scores_softmax_kernel(const float* __restrict__ biases)
{
    int bh = blockIdx.y, b = bh >> 3, h = bh & 7;
    const float* Q  = g_q   + ((size_t)b * NH_KD + h * KEY_DIM) * RES;
    const float* Kp = g_qkv + ((size_t)b * H_QKV + NH_KD + h * KEY_DIM) * RES;
    float*       S  = g_attn + (size_t)bh * RES * RES;

    __shared__ float Qs[128 * 36];   // [n][d]
    __shared__ float Ks[32 * 136];   // [d][m]
    __shared__ float red[2 * 128];
    __shared__ float rmax[128];
    __shared__ float rsum[128];

    const int t = threadIdx.x;
    const int lane = t & 31, warp = t >> 5;
    const int wm = warp >> 1, wn = warp & 1;
    const int q_ = lane >> 2;
    const int n0 = blockIdx.x * 128;

    // Q tile load (transpose scatter) — once
#pragma unroll
    for (int i = 0; i < 4; i++) {
        int f = t + 256 * i;
        int d = f >> 5, c4 = (f & 31) * 4;
        float4 q = tf4(*(const float4*)(Q + (size_t)d * RES + n0 + c4));
        Qs[(c4 + 0) * 36 + d] = q.x;
        Qs[(c4 + 1) * 36 + d] = q.y;
        Qs[(c4 + 2) * 36 + d] = q.z;
        Qs[(c4 + 3) * 36 + d] = q.w;
    }
    if (t < 128) { rmax[t] = -1e30f; rsum[t] = 0.0f; }

    const float* brow = biases + h * RES;

    // ================= PASS 1: row max =================
    for (int mt = 0; mt < 8; mt++) {
        const int m0 = mt * 128;
        __syncthreads();
#pragma unroll
        for (int i = 0; i < 4; i++) {
            int f = t + 256 * i;
            int d = f >> 5, c4 = (f & 31) * 4;
            *(float4*)(Ks + d * 136 + c4) = tf4(*(const float4*)(Kp + (size_t)d * RES + m0 + c4));
        }
        __syncthreads();

        float acc[2][8][4];
#pragma unroll
        for (int a_ = 0; a_ < 2; a_++)
#pragma unroll
            for (int j = 0; j < 8; j++)
#pragma unroll
                for (int u = 0; u < 4; u++) acc[a_][j][u] = 0.0f;
#pragma unroll
        for (int s = 0; s < 4; s++)
            mma_step<36>(Qs, Ks, s, wm, wn, lane, acc);

        float pm[2][2] = {{-1e30f, -1e30f}, {-1e30f, -1e30f}};
#pragma unroll
        for (int a_ = 0; a_ < 2; a_++) {
            int nr0 = n0 + wm * 32 + a_ * 16 + q_;
            int nr1 = nr0 + 8;
#pragma unroll
            for (int j = 0; j < 8; j++) {
                int mc = m0 + wn * 64 + j * 8 + 2 * (lane & 3);
                float v0 = acc[a_][j][0] * SCALE_QK + __ldg(&brow[abs(nr0 - mc)]);
                float v1 = acc[a_][j][1] * SCALE_QK + __ldg(&brow[abs(nr0 - mc - 1)]);
                float v2 = acc[a_][j][2] * SCALE_QK + __ldg(&brow[abs(nr1 - mc)]);
                float v3 = acc[a_][j][3] * SCALE_QK + __ldg(&brow[abs(nr1 - mc - 1)]);
                pm[a_][0] = fmaxf(pm[a_][0], fmaxf(v0, v1));
                pm[a_][1] = fmaxf(pm[a_][1], fmaxf(v2, v3));
            }
        }
#pragma unroll
        for (int a_ = 0; a_ < 2; a_++)
#pragma unroll
            for (int hh = 0; hh < 2; hh++) {
                pm[a_][hh] = fmaxf(pm[a_][hh], __shfl_xor_sync(0xffffffffu, pm[a_][hh], 1));
                pm[a_][hh] = fmaxf(pm[a_][hh], __shfl_xor_sync(0xffffffffu, pm[a_][hh], 2));
            }
        if ((lane & 3) == 0) {
#pragma unroll
            for (int a_ = 0; a_ < 2; a_++) {
                red[wn * 128 + wm * 32 + a_ * 16 + q_]     = pm[a_][0];
                red[wn * 128 + wm * 32 + a_ * 16 + q_ + 8] = pm[a_][1];
            }
        }
        __syncthreads();
        if (t < 128) rmax[t] = fmaxf(rmax[t], fmaxf(red[t], red[t + 128]));
    }
    __syncthreads();

    // ================= PASS 2: exp + sum + store =================
    for (int mt = 0; mt < 8; mt++) {
        const int m0 = mt * 128;
        __syncthreads();
#pragma unroll
        for (int i = 0; i < 4; i++) {
            int f = t + 256 * i;
            int d = f >> 5, c4 = (f & 31) * 4;
            *(float4*)(Ks + d * 136 + c4) = tf4(*(const float4*)(Kp + (size_t)d * RES + m0 + c4));
        }
        __syncthreads();

        float acc[2][8][4];
#pragma unroll
        for (int a_ = 0; a_ < 2; a_++)
#pragma unroll
            for (int j = 0; j < 8; j++)
#pragma unroll
                for (int u = 0; u < 4; u++) acc[a_][j][u] = 0.0f;
#pragma unroll
        for (int s = 0; s < 4; s++)
            mma_step<36>(Qs, Ks, s, wm, wn, lane, acc);

        float ps[2][2] = {{0.f, 0.f}, {0.f, 0.f}};
#pragma unroll
        for (int a_ = 0; a_ < 2; a_++) {
            int r0l = wm * 32 + a_ * 16 + q_;
            int nr0 = n0 + r0l;
            int nr1 = nr0 + 8;
            float rm0 = rmax[r0l];
            float rm1 = rmax[r0l + 8];
#pragma unroll
            for (int j = 0; j < 8; j++) {
                int mc = m0 + wn * 64 + j * 8 + 2 * (lane & 3);
                float v0 = acc[a_][j][0] * SCALE_QK + __ldg(&brow[abs(nr0 - mc)]);
                float v1 = acc[a_][j][1] * SCALE_QK + __ldg(&brow[abs(nr0 - mc - 1)]);
                float v2 = acc[a_][j][2] * SCALE_QK + __ldg(&brow[abs(nr1 - mc)]);
                float v3 = acc[a_][j][3] * SCALE_QK + __ldg(&brow[abs(nr1 - mc - 1)]);
                float e0 = __expf(v0 - rm0);
                float e1 = __expf(v1 - rm0);
                float e2 = __expf(v2 - rm1);
                float e3 = __expf(v3 - rm1);
                ps[a_][0] += e0 + e1;
                ps[a_][1] += e2 + e3;
                *(float2*)&S[(size_t)nr0 * RES + mc] = make_float2(e0, e1);
                *(float2*)&S[(size_t)nr1 * RES + mc] = make_float2(e2, e3);
            }
        }
#pragma unroll
        for (int a_ = 0; a_ < 2; a_++)
#pragma unroll
            for (int hh = 0; hh < 2; hh++) {
                ps[a_][hh] += __shfl_xor_sync(0xffffffffu, ps[a_][hh], 1);
                ps[a_][hh] += __shfl_xor_sync(0xffffffffu, ps[a_][hh], 2);
            }
        if ((lane & 3) == 0) {
#pragma unroll
            for (int a_ = 0; a_ < 2; a_++) {
                red[wn * 128 + wm * 32 + a_ * 16 + q_]     = ps[a_][0];
                red[wn * 128 + wm * 32 + a_ * 16 + q_ + 8] = ps[a_][1];
            }
        }
        __syncthreads();
        if (t < 128) rsum[t] += red[t] + red[t + 128];
    }
    __syncthreads();
    if (t < 128) g_rsum[(size_t)bh * RES + n0 + t] = rsum[t];
}

// =====================================================================
// AV: O[d][n] = (sum_m V[d][m] * E[n][m]) / rsum[n]. 128x128, K=1024.
// =====================================================================
__global__ void __launch_bounds__(256, 2)
av_kernel()
{
    int bh = blockIdx.z, b = bh >> 3, h = bh & 7;
    const float* V = g_qkv + ((size_t)b * H_QKV + 2 * NH_KD + h * D_HEAD) * RES;
    const float* P = g_attn + (size_t)bh * RES * RES;
    float*       O = g_av  + ((size_t)b * DH + h * D_HEAD) * RES;

    __shared__ float As[2][128 * 20];
    __shared__ float Bs[2][16 * 136];

    const int t = threadIdx.x;
    const int lane = t & 31, warp = t >> 5;
    const int wm = warp >> 1, wn = warp & 1;
    const int n0 = blockIdx.x * 128;

    const int am  = t >> 1;
    const int akc = (t & 1) * 8;

    const float* Vptr = V + (size_t)am * RES + akc;
    const float* Pptr = P + (size_t)(n0 + am) * RES + akc;

    float acc[2][8][4];
#pragma unroll
    for (int a_ = 0; a_ < 2; a_++)
#pragma unroll
        for (int j = 0; j < 8; j++)
#pragma unroll
            for (int u = 0; u < 4; u++) acc[a_][j][u] = 0.0f;

    {
        float4 v0 = *(const float4*)(Vptr);
        float4 v1 = *(const float4*)(Vptr + 4);
        *(float4*)(As[0] + am * 20 + akc)     = tf4(v0);
        *(float4*)(As[0] + am * 20 + akc + 4) = tf4(v1);
        float4 p0 = tf4(*(const float4*)(Pptr));
        float4 p1 = tf4(*(const float4*)(Pptr + 4));
        Bs[0][(akc + 0) * 136 + am] = p0.x;
        Bs[0][(akc + 1) * 136 + am] = p0.y;
        Bs[0][(akc + 2) * 136 + am] = p0.z;
        Bs[0][(akc + 3) * 136 + am] = p0.w;
        Bs[0][(akc + 4) * 136 + am] = p1.x;
        Bs[0][(akc + 5) * 136 + am] = p1.y;
        Bs[0][(akc + 6) * 136 + am] = p1.z;
        Bs[0][(akc + 7) * 136 + am] = p1.w;
    }
    __syncthreads();

    int buf = 0;
    for (int m0 = 16; m0 < RES; m0 += 16) {
        float4 pv0 = *(const float4*)(Vptr + m0);
        float4 pv1 = *(const float4*)(Vptr + m0 + 4);
        float4 pp0 = *(const float4*)(Pptr + m0);
        float4 pp1 = *(const float4*)(Pptr + m0 + 4);

        mma_step<20>(As[buf], Bs[buf], 0, wm, wn, lane, acc);
        mma_step<20>(As[buf], Bs[buf], 1, wm, wn, lane, acc);

        int nb = buf ^ 1;
        *(float4*)(As[nb] + am * 20 + akc)     = tf4(pv0);
        *(float4*)(As[nb] + am * 20 + akc + 4) = tf4(pv1);
        pp0 = tf4(pp0); pp1 = tf4(pp1);
        Bs[nb][(akc + 0) * 136 + am] = pp0.x;
        Bs[nb][(akc + 1) * 136 + am] = pp0.y;
        Bs[nb][(akc + 2) * 136 + am] = pp0.z;
        Bs[nb][(akc + 3) * 136 + am] = pp0.w;
        Bs[nb][(akc + 4) * 136 + am] = pp1.x;
        Bs[nb][(akc + 5) * 136 + am] = pp1.y;
        Bs[nb][(akc + 6) * 136 + am] = pp1.z;
        Bs[nb][(akc + 7) * 136 + am] = pp1.w;
        __syncthreads();
        buf = nb;
    }
    mma_step<20>(As[buf], Bs[buf], 0, wm, wn, lane, acc);
    mma_step<20>(As[buf], Bs[buf], 1, wm, wn, lane, acc);

    // normalization factors per n-column
    const float* rs = g_rsum + (size_t)bh * RES + n0;
    float2 invj[8];
#pragma unroll
    for (int j = 0; j < 8; j++) {
        int col = wn * 64 + j * 8 + 2 * (lane & 3);
        float2 s = *(const float2*)&rs[col];
        invj[j] = make_float2(1.0f / s.x, 1.0f / s.y);
    }

#pragma unroll
    for (int a_ = 0; a_ < 2; a_++) {
        int r0 = wm * 32 + a_ * 16 + (lane >> 2);
        int r1 = r0 + 8;
#pragma unroll
        for (int j = 0; j < 8; j++) {
            int col = n0 + wn * 64 + j * 8 + 2 * (lane & 3);
            *(float2*)&O[(size_t)r0 * RES + col] =
                make_float2(acc[a_][j][0] * invj[j].x, acc[a_][j][1] * invj[j].y);
            *(float2*)&O[(size_t)r1 * RES + col] =
                make_float2(acc[a_][j][2] * invj[j].x, acc[a_][j][3] * invj[j].y);
        }
    }
}

// =====================================================================
extern "C" void kernel_launch(void* const* d_in, const int* in_sizes, int n_in,
                              void* d_out, int out_size)
{
    const float* x       = (const float*)d_in[0];
    const float* w_qkv   = (const float*)d_in[1];
    const float* qkv_g   = (const float*)d_in[2];
    const float* qkv_b   = (const float*)d_in[3];
    const float* qkv_m   = (const float*)d_in[4];
    const float* qkv_v   = (const float*)d_in[5];
    const float* w_dw    = (const float*)d_in[6];
    const float* dw_g    = (const float*)d_in[7];
    const float* dw_b    = (const float*)d_in[8];
    const float* dw_m    = (const float*)d_in[9];
    const float* dw_v    = (const float*)d_in[10];
    const float* w_proj  = (const float*)d_in[11];
    const float* proj_g  = (const float*)d_in[12];
    const float* proj_b  = (const float*)d_in[13];
    const float* proj_m  = (const float*)d_in[14];
    const float* proj_v  = (const float*)d_in[15];
    const float* biases  = (const float*)d_in[16];
    float* out = (float*)d_out;

    qkv_gemm_kernel<<<dim3(RES / 128, H_QKV / 128, B_SZ), 256>>>(x, w_qkv, qkv_g, qkv_b, qkv_m, qkv_v);
    dwconv_kernel<<<B_SZ * NH_KD, 256>>>(w_dw, dw_g, dw_b, dw_m, dw_v);
    scores_softmax_kernel<<<dim3(RES / 128, B_SZ * NUM_HEADS), 256>>>(biases);
    av_kernel<<<dim3(RES / 128, 1, B_SZ * NUM_HEADS), 256>>>();
    proj_gemm_kernel<<<dim3(RES / 128, DIM / 128, B_SZ), 256>>>(w_proj, out, proj_g, proj_b, proj_m, proj_v);
}

// round 14
// speedup vs baseline: 1.0021x; 1.0008x over previous
#include <cuda_runtime.h>
#include <math.h>

#define B_SZ      16
#define DIM       512
#define KEY_DIM   32
#define NUM_HEADS 8
#define RES       1024
#define NH_KD     256
#define D_HEAD    128
#define DH        1024
#define H_QKV     1536
#define EPS       1e-5f
#define SCALE_QK  0.17677669529663687f

// ---------------- static scratch ----------------
__device__ float g_qkv [B_SZ * H_QKV * RES];
__device__ float g_q   [B_SZ * NH_KD * RES];
__device__ float g_attn[134217728];           // 16*8*1024*1024 (unnormalized exp)
__device__ float g_av  [B_SZ * DH * RES];
__device__ float g_rsum[B_SZ * NUM_HEADS * RES];

// ---------------- tf32 helpers ----------------
__device__ __forceinline__ unsigned f2tf(float f) {
    unsigned r;
    asm("cvt.rna.tf32.f32 %0, %1;" : "=r"(r) : "f"(f));
    return r;
}
__device__ __forceinline__ float4 tf4(float4 v) {
    v.x = __uint_as_float(f2tf(v.x));
    v.y = __uint_as_float(f2tf(v.y));
    v.z = __uint_as_float(f2tf(v.z));
    v.w = __uint_as_float(f2tf(v.w));
    return v;
}
__device__ __forceinline__ void mma8(float c[4], const unsigned a[4],
                                     unsigned b0, unsigned b1) {
    asm("mma.sync.aligned.m16n8k8.row.col.f32.tf32.tf32.f32 "
        "{%0,%1,%2,%3},{%4,%5,%6,%7},{%8,%9},{%0,%1,%2,%3};"
        : "+f"(c[0]), "+f"(c[1]), "+f"(c[2]), "+f"(c[3])
        : "r"(a[0]), "r"(a[1]), "r"(a[2]), "r"(a[3]), "r"(b0), "r"(b1));
}

// ---------------- warp-tile mma step ----------------
// as: [m][k] stride AS; bs: [k][n] stride 136. One k8 step.
template<int AS>
__device__ __forceinline__ void mma_step(const float* __restrict__ as,
                                         const float* __restrict__ bs,
                                         int s, int wm, int wn, int lane,
                                         float acc[2][8][4])
{
    unsigned afr[2][4];
    const int kk = s * 8 + (lane & 3);
#pragma unroll
    for (int a_ = 0; a_ < 2; a_++) {
        int mr = wm * 32 + a_ * 16 + (lane >> 2);
        afr[a_][0] = __float_as_uint(as[mr * AS + kk]);
        afr[a_][1] = __float_as_uint(as[(mr + 8) * AS + kk]);
        afr[a_][2] = __float_as_uint(as[mr * AS + kk + 4]);
        afr[a_][3] = __float_as_uint(as[(mr + 8) * AS + kk + 4]);
    }
#pragma unroll
    for (int j = 0; j < 8; j++) {
        int col = wn * 64 + j * 8 + (lane >> 2);
        unsigned b0 = __float_as_uint(bs[(s * 8 + (lane & 3)) * 136 + col]);
        unsigned b1 = __float_as_uint(bs[(s * 8 + (lane & 3) + 4) * 136 + col]);
        mma8(acc[0][j], afr[0], b0, b1);
        mma8(acc[1][j], afr[1], b0, b1);
    }
}

// =====================================================================
// Channel GEMM+BN: 128x128 tile, double-buffered tf32 mma.
// =====================================================================
template<bool RELU_B>
__device__ __forceinline__ void gemm_body(
    const float* __restrict__ A, const float* __restrict__ Bm, float* __restrict__ C,
    int N, int K, size_t sB, size_t sC,
    const float* __restrict__ gg, const float* __restrict__ bbp,
    const float* __restrict__ mmp, const float* __restrict__ vvp)
{
    __shared__ float As[2][128 * 20];
    __shared__ float Bs[2][16 * 136];
    const float* Bb = Bm + (size_t)blockIdx.z * sB;
    float*       Cb = C  + (size_t)blockIdx.z * sC;

    const int t = threadIdx.x;
    const int lane = t & 31, warp = t >> 5;
    const int wm = warp >> 1, wn = warp & 1;
    const int row0 = blockIdx.y * 128, col0 = blockIdx.x * 128;

    const int am  = t >> 1;
    const int akc = (t & 1) * 8;
    const int bkr = t >> 5;
    const int bc4 = (t & 31) * 4;

    const float* Aptr  = A  + (size_t)(row0 + am) * K + akc;
    const float* Bptr0 = Bb + (size_t)bkr * N + col0 + bc4;
    const float* Bptr1 = Bb + (size_t)(bkr + 8) * N + col0 + bc4;

    float acc[2][8][4];
#pragma unroll
    for (int a_ = 0; a_ < 2; a_++)
#pragma unroll
        for (int j = 0; j < 8; j++)
#pragma unroll
            for (int u = 0; u < 4; u++) acc[a_][j][u] = 0.0f;

    {
        float4 a0 = *(const float4*)(Aptr);
        float4 a1 = *(const float4*)(Aptr + 4);
        *(float4*)(As[0] + am * 20 + akc)     = tf4(a0);
        *(float4*)(As[0] + am * 20 + akc + 4) = tf4(a1);
        float4 b0 = *(const float4*)(Bptr0);
        float4 b1 = *(const float4*)(Bptr1);
        if (RELU_B) {
            b0.x = fmaxf(b0.x, 0.f); b0.y = fmaxf(b0.y, 0.f); b0.z = fmaxf(b0.z, 0.f); b0.w = fmaxf(b0.w, 0.f);
            b1.x = fmaxf(b1.x, 0.f); b1.y = fmaxf(b1.y, 0.f); b1.z = fmaxf(b1.z, 0.f); b1.w = fmaxf(b1.w, 0.f);
        }
        *(float4*)(Bs[0] + bkr * 136 + bc4)       = tf4(b0);
        *(float4*)(Bs[0] + (bkr + 8) * 136 + bc4) = tf4(b1);
    }
    __syncthreads();

    int buf = 0;
    for (int k0 = 16; k0 < K; k0 += 16) {
        float4 pa0 = *(const float4*)(Aptr + k0);
        float4 pa1 = *(const float4*)(Aptr + k0 + 4);
        float4 pb0 = *(const float4*)(Bptr0 + (size_t)k0 * N);
        float4 pb1 = *(const float4*)(Bptr1 + (size_t)k0 * N);

        mma_step<20>(As[buf], Bs[buf], 0, wm, wn, lane, acc);
        mma_step<20>(As[buf], Bs[buf], 1, wm, wn, lane, acc);

        if (RELU_B) {
            pb0.x = fmaxf(pb0.x, 0.f); pb0.y = fmaxf(pb0.y, 0.f); pb0.z = fmaxf(pb0.z, 0.f); pb0.w = fmaxf(pb0.w, 0.f);
            pb1.x = fmaxf(pb1.x, 0.f); pb1.y = fmaxf(pb1.y, 0.f); pb1.z = fmaxf(pb1.z, 0.f); pb1.w = fmaxf(pb1.w, 0.f);
        }
        int nb = buf ^ 1;
        *(float4*)(As[nb] + am * 20 + akc)        = tf4(pa0);
        *(float4*)(As[nb] + am * 20 + akc + 4)    = tf4(pa1);
        *(float4*)(Bs[nb] + bkr * 136 + bc4)      = tf4(pb0);
        *(float4*)(Bs[nb] + (bkr + 8) * 136 + bc4)= tf4(pb1);
        __syncthreads();
        buf = nb;
    }
    mma_step<20>(As[buf], Bs[buf], 0, wm, wn, lane, acc);
    mma_step<20>(As[buf], Bs[buf], 1, wm, wn, lane, acc);

#pragma unroll
    for (int a_ = 0; a_ < 2; a_++) {
        int r0 = row0 + wm * 32 + a_ * 16 + (lane >> 2);
        int r1 = r0 + 8;
        float inv0  = gg[r0] * rsqrtf(vvp[r0] + EPS);
        float beta0 = bbp[r0] - mmp[r0] * inv0;
        float inv1  = gg[r1] * rsqrtf(vvp[r1] + EPS);
        float beta1 = bbp[r1] - mmp[r1] * inv1;
#pragma unroll
        for (int j = 0; j < 8; j++) {
            int col = col0 + wn * 64 + j * 8 + 2 * (lane & 3);
            float2 w0 = make_float2(acc[a_][j][0] * inv0 + beta0,
                                    acc[a_][j][1] * inv0 + beta0);
            float2 w1 = make_float2(acc[a_][j][2] * inv1 + beta1,
                                    acc[a_][j][3] * inv1 + beta1);
            *(float2*)&Cb[(size_t)r0 * N + col] = w0;
            *(float2*)&Cb[(size_t)r1 * N + col] = w1;
        }
    }
}

__global__ void __launch_bounds__(256, 2)
qkv_gemm_kernel(const float* __restrict__ x, const float* __restrict__ w,
                const float* __restrict__ g, const float* __restrict__ b,
                const float* __restrict__ m, const float* __restrict__ v)
{
    gemm_body<false>(w, x, g_qkv, RES, DIM,
                     (size_t)DIM * RES, (size_t)H_QKV * RES, g, b, m, v);
}

__global__ void __launch_bounds__(256, 2)
proj_gemm_kernel(const float* __restrict__ w, float* __restrict__ out,
                 const float* __restrict__ g, const float* __restrict__ b,
                 const float* __restrict__ m, const float* __restrict__ v)
{
    gemm_body<true>(w, g_av, out, RES, DH,
                    (size_t)DH * RES, (size_t)DIM * RES, g, b, m, v);
}

// =====================================================================
// Depthwise conv3 + BN on q channels.
// =====================================================================
__global__ void __launch_bounds__(256)
dwconv_kernel(const float* __restrict__ w_dw,
              const float* __restrict__ dg, const float* __restrict__ db,
              const float* __restrict__ dm, const float* __restrict__ dv)
{
    int bc = blockIdx.x;
    int b = bc >> 8, c = bc & 255;
    const float* in  = g_qkv + ((size_t)b * H_QKV + c) * RES;
    float*       out = g_q   + ((size_t)b * NH_KD + c) * RES;

    __shared__ float s[RES + 2];
    int tid = threadIdx.x;
    for (int i = tid; i < RES; i += 256) s[i + 1] = in[i];
    if (tid == 0) { s[0] = 0.0f; s[RES + 1] = 0.0f; }
    __syncthreads();

    float w0 = w_dw[c * 3 + 0], w1 = w_dw[c * 3 + 1], w2 = w_dw[c * 3 + 2];
    float inv  = dg[c] * rsqrtf(dv[c] + EPS);
    float beta = db[c] - dm[c] * inv;
    for (int i = tid; i < RES; i += 256) {
        float y = w0 * s[i] + w1 * s[i + 1] + w2 * s[i + 2];
        out[i] = y * inv + beta;
    }
}

// =====================================================================
// Fused scores + softmax (2-pass recompute).
// Pass 1: row max of (q.k*scale + bias) over all m.
// Pass 2: write exp(s - max) unnormalized, accumulate row sums -> g_rsum.
// Block: n-tile 128 rows, loops 8 m-tiles of 128. grid (8, 128 bh).
// =====================================================================
__global__ void __launch_bounds__(256, 2)
scores_softmax_kernel(const float* __restrict__ biases)
{
    int bh = blockIdx.y, b = bh >> 3, h = bh & 7;
    const float* Q  = g_q   + ((size_t)b * NH_KD + h * KEY_DIM) * RES;
    const float* Kp = g_qkv + ((size_t)b * H_QKV + NH_KD + h * KEY_DIM) * RES;
    float*       S  = g_attn + (size_t)bh * RES * RES;

    __shared__ float Qs[128 * 36];   // [n][d]
    __shared__ float Ks[32 * 136];   // [d][m]
    __shared__ float red[2 * 128];
    __shared__ float rmax[128];
    __shared__ float rsum[128];

    const int t = threadIdx.x;
    const int lane = t & 31, warp = t >> 5;
    const int wm = warp >> 1, wn = warp & 1;
    const int q_ = lane >> 2;
    const int n0 = blockIdx.x * 128;

    // Q tile load (transpose scatter) — once
#pragma unroll
    for (int i = 0; i < 4; i++) {
        int f = t + 256 * i;
        int d = f >> 5, c4 = (f & 31) * 4;
        float4 q = tf4(*(const float4*)(Q + (size_t)d * RES + n0 + c4));
        Qs[(c4 + 0) * 36 + d] = q.x;
        Qs[(c4 + 1) * 36 + d] = q.y;
        Qs[(c4 + 2) * 36 + d] = q.z;
        Qs[(c4 + 3) * 36 + d] = q.w;
    }
    if (t < 128) { rmax[t] = -1e30f; rsum[t] = 0.0f; }

    const float* brow = biases + h * RES;

    // ================= PASS 1: row max =================
    for (int mt = 0; mt < 8; mt++) {
        const int m0 = mt * 128;
        __syncthreads();
#pragma unroll
        for (int i = 0; i < 4; i++) {
            int f = t + 256 * i;
            int d = f >> 5, c4 = (f & 31) * 4;
            *(float4*)(Ks + d * 136 + c4) = tf4(*(const float4*)(Kp + (size_t)d * RES + m0 + c4));
        }
        __syncthreads();

        float acc[2][8][4];
#pragma unroll
        for (int a_ = 0; a_ < 2; a_++)
#pragma unroll
            for (int j = 0; j < 8; j++)
#pragma unroll
                for (int u = 0; u < 4; u++) acc[a_][j][u] = 0.0f;
#pragma unroll
        for (int s = 0; s < 4; s++)
            mma_step<36>(Qs, Ks, s, wm, wn, lane, acc);

        float pm[2][2] = {{-1e30f, -1e30f}, {-1e30f, -1e30f}};
#pragma unroll
        for (int a_ = 0; a_ < 2; a_++) {
            int nr0 = n0 + wm * 32 + a_ * 16 + q_;
            int nr1 = nr0 + 8;
#pragma unroll
            for (int j = 0; j < 8; j++) {
                int mc = m0 + wn * 64 + j * 8 + 2 * (lane & 3);
                float v0 = acc[a_][j][0] * SCALE_QK + __ldg(&brow[abs(nr0 - mc)]);
                float v1 = acc[a_][j][1] * SCALE_QK + __ldg(&brow[abs(nr0 - mc - 1)]);
                float v2 = acc[a_][j][2] * SCALE_QK + __ldg(&brow[abs(nr1 - mc)]);
                float v3 = acc[a_][j][3] * SCALE_QK + __ldg(&brow[abs(nr1 - mc - 1)]);
                pm[a_][0] = fmaxf(pm[a_][0], fmaxf(v0, v1));
                pm[a_][1] = fmaxf(pm[a_][1], fmaxf(v2, v3));
            }
        }
#pragma unroll
        for (int a_ = 0; a_ < 2; a_++)
#pragma unroll
            for (int hh = 0; hh < 2; hh++) {
                pm[a_][hh] = fmaxf(pm[a_][hh], __shfl_xor_sync(0xffffffffu, pm[a_][hh], 1));
                pm[a_][hh] = fmaxf(pm[a_][hh], __shfl_xor_sync(0xffffffffu, pm[a_][hh], 2));
            }
        if ((lane & 3) == 0) {
#pragma unroll
            for (int a_ = 0; a_ < 2; a_++) {
                red[wn * 128 + wm * 32 + a_ * 16 + q_]     = pm[a_][0];
                red[wn * 128 + wm * 32 + a_ * 16 + q_ + 8] = pm[a_][1];
            }
        }
        __syncthreads();
        if (t < 128) rmax[t] = fmaxf(rmax[t], fmaxf(red[t], red[t + 128]));
    }
    __syncthreads();

    // ================= PASS 2: exp + sum + store =================
    for (int mt = 0; mt < 8; mt++) {
        const int m0 = mt * 128;
        __syncthreads();
#pragma unroll
        for (int i = 0; i < 4; i++) {
            int f = t + 256 * i;
            int d = f >> 5, c4 = (f & 31) * 4;
            *(float4*)(Ks + d * 136 + c4) = tf4(*(const float4*)(Kp + (size_t)d * RES + m0 + c4));
        }
        __syncthreads();

        float acc[2][8][4];
#pragma unroll
        for (int a_ = 0; a_ < 2; a_++)
#pragma unroll
            for (int j = 0; j < 8; j++)
#pragma unroll
                for (int u = 0; u < 4; u++) acc[a_][j][u] = 0.0f;
#pragma unroll
        for (int s = 0; s < 4; s++)
            mma_step<36>(Qs, Ks, s, wm, wn, lane, acc);

        float ps[2][2] = {{0.f, 0.f}, {0.f, 0.f}};
#pragma unroll
        for (int a_ = 0; a_ < 2; a_++) {
            int r0l = wm * 32 + a_ * 16 + q_;
            int nr0 = n0 + r0l;
            int nr1 = nr0 + 8;
            float rm0 = rmax[r0l];
            float rm1 = rmax[r0l + 8];
#pragma unroll
            for (int j = 0; j < 8; j++) {
                int mc = m0 + wn * 64 + j * 8 + 2 * (lane & 3);
                float v0 = acc[a_][j][0] * SCALE_QK + __ldg(&brow[abs(nr0 - mc)]);
                float v1 = acc[a_][j][1] * SCALE_QK + __ldg(&brow[abs(nr0 - mc - 1)]);
                float v2 = acc[a_][j][2] * SCALE_QK + __ldg(&brow[abs(nr1 - mc)]);
                float v3 = acc[a_][j][3] * SCALE_QK + __ldg(&brow[abs(nr1 - mc - 1)]);
                float e0 = __expf(v0 - rm0);
                float e1 = __expf(v1 - rm0);
                float e2 = __expf(v2 - rm1);
                float e3 = __expf(v3 - rm1);
                ps[a_][0] += e0 + e1;
                ps[a_][1] += e2 + e3;
                *(float2*)&S[(size_t)nr0 * RES + mc] = make_float2(e0, e1);
                *(float2*)&S[(size_t)nr1 * RES + mc] = make_float2(e2, e3);
            }
        }
#pragma unroll
        for (int a_ = 0; a_ < 2; a_++)
#pragma unroll
            for (int hh = 0; hh < 2; hh++) {
                ps[a_][hh] += __shfl_xor_sync(0xffffffffu, ps[a_][hh], 1);
                ps[a_][hh] += __shfl_xor_sync(0xffffffffu, ps[a_][hh], 2);
            }
        if ((lane & 3) == 0) {
#pragma unroll
            for (int a_ = 0; a_ < 2; a_++) {
                red[wn * 128 + wm * 32 + a_ * 16 + q_]     = ps[a_][0];
                red[wn * 128 + wm * 32 + a_ * 16 + q_ + 8] = ps[a_][1];
            }
        }
        __syncthreads();
        if (t < 128) rsum[t] += red[t] + red[t + 128];
    }
    __syncthreads();
    if (t < 128) g_rsum[(size_t)bh * RES + n0 + t] = rsum[t];
}

// =====================================================================
// AV: O[d][n] = (sum_m V[d][m] * E[n][m]) / rsum[n]. 128x128, K=1024.
// =====================================================================
__global__ void __launch_bounds__(256, 2)
av_kernel()
{
    int bh = blockIdx.z, b = bh >> 3, h = bh & 7;
    const float* V = g_qkv + ((size_t)b * H_QKV + 2 * NH_KD + h * D_HEAD) * RES;
    const float* P = g_attn + (size_t)bh * RES * RES;
    float*       O = g_av  + ((size_t)b * DH + h * D_HEAD) * RES;

    __shared__ float As[2][128 * 20];
    __shared__ float Bs[2][16 * 136];

    const int t = threadIdx.x;
    const int lane = t & 31, warp = t >> 5;
    const int wm = warp >> 1, wn = warp & 1;
    const int n0 = blockIdx.x * 128;

    const int am  = t >> 1;
    const int akc = (t & 1) * 8;

    const float* Vptr = V + (size_t)am * RES + akc;
    const float* Pptr = P + (size_t)(n0 + am) * RES + akc;

    float acc[2][8][4];
#pragma unroll
    for (int a_ = 0; a_ < 2; a_++)
#pragma unroll
        for (int j = 0; j < 8; j++)
#pragma unroll
            for (int u = 0; u < 4; u++) acc[a_][j][u] = 0.0f;

    {
        float4 v0 = *(const float4*)(Vptr);
        float4 v1 = *(const float4*)(Vptr + 4);
        *(float4*)(As[0] + am * 20 + akc)     = tf4(v0);
        *(float4*)(As[0] + am * 20 + akc + 4) = tf4(v1);
        float4 p0 = tf4(*(const float4*)(Pptr));
        float4 p1 = tf4(*(const float4*)(Pptr + 4));
        Bs[0][(akc + 0) * 136 + am] = p0.x;
        Bs[0][(akc + 1) * 136 + am] = p0.y;
        Bs[0][(akc + 2) * 136 + am] = p0.z;
        Bs[0][(akc + 3) * 136 + am] = p0.w;
        Bs[0][(akc + 4) * 136 + am] = p1.x;
        Bs[0][(akc + 5) * 136 + am] = p1.y;
        Bs[0][(akc + 6) * 136 + am] = p1.z;
        Bs[0][(akc + 7) * 136 + am] = p1.w;
    }
    __syncthreads();

    int buf = 0;
    for (int m0 = 16; m0 < RES; m0 += 16) {
        float4 pv0 = *(const float4*)(Vptr + m0);
        float4 pv1 = *(const float4*)(Vptr + m0 + 4);
        float4 pp0 = *(const float4*)(Pptr + m0);
        float4 pp1 = *(const float4*)(Pptr + m0 + 4);

        mma_step<20>(As[buf], Bs[buf], 0, wm, wn, lane, acc);
        mma_step<20>(As[buf], Bs[buf], 1, wm, wn, lane, acc);

        int nb = buf ^ 1;
        *(float4*)(As[nb] + am * 20 + akc)     = tf4(pv0);
        *(float4*)(As[nb] + am * 20 + akc + 4) = tf4(pv1);
        pp0 = tf4(pp0); pp1 = tf4(pp1);
        Bs[nb][(akc + 0) * 136 + am] = pp0.x;
        Bs[nb][(akc + 1) * 136 + am] = pp0.y;
        Bs[nb][(akc + 2) * 136 + am] = pp0.z;
        Bs[nb][(akc + 3) * 136 + am] = pp0.w;
        Bs[nb][(akc + 4) * 136 + am] = pp1.x;
        Bs[nb][(akc + 5) * 136 + am] = pp1.y;
        Bs[nb][(akc + 6) * 136 + am] = pp1.z;
        Bs[nb][(akc + 7) * 136 + am] = pp1.w;
        __syncthreads();
        buf = nb;
    }
    mma_step<20>(As[buf], Bs[buf], 0, wm, wn, lane, acc);
    mma_step<20>(As[buf], Bs[buf], 1, wm, wn, lane, acc);

    // normalization factors per n-column
    const float* rs = g_rsum + (size_t)bh * RES + n0;
    float2 invj[8];
#pragma unroll
    for (int j = 0; j < 8; j++) {
        int col = wn * 64 + j * 8 + 2 * (lane & 3);
        float2 s = *(const float2*)&rs[col];
        invj[j] = make_float2(1.0f / s.x, 1.0f / s.y);
    }

#pragma unroll
    for (int a_ = 0; a_ < 2; a_++) {
        int r0 = wm * 32 + a_ * 16 + (lane >> 2);
        int r1 = r0 + 8;
#pragma unroll
        for (int j = 0; j < 8; j++) {
            int col = n0 + wn * 64 + j * 8 + 2 * (lane & 3);
            *(float2*)&O[(size_t)r0 * RES + col] =
                make_float2(acc[a_][j][0] * invj[j].x, acc[a_][j][1] * invj[j].y);
            *(float2*)&O[(size_t)r1 * RES + col] =
                make_float2(acc[a_][j][2] * invj[j].x, acc[a_][j][3] * invj[j].y);
        }
    }
}

// =====================================================================
extern "C" void kernel_launch(void* const* d_in, const int* in_sizes, int n_in,
                              void* d_out, int out_size)
{
    const float* x       = (const float*)d_in[0];
    const float* w_qkv   = (const float*)d_in[1];
    const float* qkv_g   = (const float*)d_in[2];
    const float* qkv_b   = (const float*)d_in[3];
    const float* qkv_m   = (const float*)d_in[4];
    const float* qkv_v   = (const float*)d_in[5];
    const float* w_dw    = (const float*)d_in[6];
    const float* dw_g    = (const float*)d_in[7];
    const float* dw_b    = (const float*)d_in[8];
    const float* dw_m    = (const float*)d_in[9];
    const float* dw_v    = (const float*)d_in[10];
    const float* w_proj  = (const float*)d_in[11];
    const float* proj_g  = (const float*)d_in[12];
    const float* proj_b  = (const float*)d_in[13];
    const float* proj_m  = (const float*)d_in[14];
    const float* proj_v  = (const float*)d_in[15];
    const float* biases  = (const float*)d_in[16];
    float* out = (float*)d_out;

    qkv_gemm_kernel<<<dim3(RES / 128, H_QKV / 128, B_SZ), 256>>>(x, w_qkv, qkv_g, qkv_b, qkv_m, qkv_v);
    dwconv_kernel<<<B_SZ * NH_KD, 256>>>(w_dw, dw_g, dw_b, dw_m, dw_v);
    scores_softmax_kernel<<<dim3(RES / 128, B_SZ * NUM_HEADS), 256>>>(biases);
    av_kernel<<<dim3(RES / 128, 1, B_SZ * NUM_HEADS), 256>>>();
    proj_gemm_kernel<<<dim3(RES / 128, DIM / 128, B_SZ), 256>>>(w_proj, out, proj_g, proj_b, proj_m, proj_v);
}